// round 1
// baseline (speedup 1.0000x reference)
#include <cuda_runtime.h>
#include <cuda_bf16.h>
#include <mma.h>

using namespace nvcuda;

// Problem constants
#define BATCH   2
#define SEQ     2048
#define DMODEL  1024
#define NHEADS  16
#define DK      64
#define BH      (BATCH * NHEADS)          // 32
#define MTOT    (BATCH * SEQ)             // 4096

// Scratch for Q, K, V in [b,h,s,d] layout (bh-major)
__device__ float g_Q[(size_t)BH * SEQ * DK];
__device__ float g_K[(size_t)BH * SEQ * DK];
__device__ float g_V[(size_t)BH * SEQ * DK];

// ---------------------------------------------------------------------------
// Kernel 1: QKV projection GEMMs.  out[m,n] = sum_k X[m,k] * W[k,n] + b[n]
// Tile 64x64, BK=32, tf32 WMMA, 256 threads (8 warps, each 32x16 of C).
// Epilogue scatters into [bh, s, d] scratch layout.
// ---------------------------------------------------------------------------
__global__ __launch_bounds__(256)
void qkv_gemm_kernel(const float* __restrict__ X,
                     const float* __restrict__ Wq, const float* __restrict__ bq,
                     const float* __restrict__ Wk, const float* __restrict__ bk,
                     const float* __restrict__ Wv, const float* __restrict__ bv)
{
    const float* W;
    const float* bias;
    float* Out;
    if (blockIdx.z == 0)      { W = Wq; bias = bq; Out = g_Q; }
    else if (blockIdx.z == 1) { W = Wk; bias = bk; Out = g_K; }
    else                      { W = Wv; bias = bv; Out = g_V; }

    __shared__ float As[64][36];   // 64 x 32, pad to 36 (float4-aligned rows)
    __shared__ float Bs[32][72];   // 32 x 64, pad to 72
    __shared__ float Cs[64][68];   // epilogue staging

    const int m0  = blockIdx.y * 64;
    const int n0  = blockIdx.x * 64;
    const int tid = threadIdx.x;
    const int warp = tid >> 5;
    const int wm = warp >> 2;      // 0..1  (rows wm*32 .. +32)
    const int wn = warp & 3;       // 0..3  (cols wn*16 .. +16)

    wmma::fragment<wmma::accumulator, 16, 16, 8, float> acc[2];
    wmma::fill_fragment(acc[0], 0.0f);
    wmma::fill_fragment(acc[1], 0.0f);

    for (int k0 = 0; k0 < DMODEL; k0 += 32) {
        // Load A tile: 64x32 = 512 float4
        #pragma unroll
        for (int it = 0; it < 2; it++) {
            int idx = tid + it * 256;
            int r = idx >> 3, c4 = idx & 7;
            float4 v = *reinterpret_cast<const float4*>(&X[(size_t)(m0 + r) * DMODEL + k0 + c4 * 4]);
            *reinterpret_cast<float4*>(&As[r][c4 * 4]) = v;
        }
        // Load B tile: 32x64 = 512 float4
        #pragma unroll
        for (int it = 0; it < 2; it++) {
            int idx = tid + it * 256;
            int r = idx >> 4, c4 = idx & 15;
            float4 v = *reinterpret_cast<const float4*>(&W[(size_t)(k0 + r) * DMODEL + n0 + c4 * 4]);
            *reinterpret_cast<float4*>(&Bs[r][c4 * 4]) = v;
        }
        __syncthreads();

        #pragma unroll
        for (int kk = 0; kk < 4; kk++) {
            wmma::fragment<wmma::matrix_b, 16, 16, 8, wmma::precision::tf32, wmma::row_major> bf;
            wmma::load_matrix_sync(bf, &Bs[kk * 8][wn * 16], 72);
            #pragma unroll
            for (int t = 0; t < bf.num_elements; t++) bf.x[t] = wmma::__float_to_tf32(bf.x[t]);
            #pragma unroll
            for (int i = 0; i < 2; i++) {
                wmma::fragment<wmma::matrix_a, 16, 16, 8, wmma::precision::tf32, wmma::row_major> af;
                wmma::load_matrix_sync(af, &As[wm * 32 + i * 16][kk * 8], 36);
                #pragma unroll
                for (int t = 0; t < af.num_elements; t++) af.x[t] = wmma::__float_to_tf32(af.x[t]);
                wmma::mma_sync(acc[i], af, bf, acc[i]);
            }
        }
        __syncthreads();
    }

    // Epilogue via smem, add bias, scatter to [bh, s, d]
    wmma::store_matrix_sync(&Cs[wm * 32 + 0][wn * 16],  acc[0], 68, wmma::mem_row_major);
    wmma::store_matrix_sync(&Cs[wm * 32 + 16][wn * 16], acc[1], 68, wmma::mem_row_major);
    __syncthreads();

    const int b  = m0 / SEQ;          // BM=64 divides SEQ, no tile crosses batch
    const int s0 = m0 % SEQ;
    const int h  = n0 / DK;           // BN=64 == DK, tile aligns to one head
    float* dst = Out + ((size_t)(b * NHEADS + h) * SEQ + s0) * DK;

    for (int idx = tid; idx < 64 * 64; idx += 256) {
        int r = idx >> 6, c = idx & 63;
        dst[(size_t)r * DK + c] = Cs[r][c] + bias[n0 + c];
    }
}

// ---------------------------------------------------------------------------
// Kernel 2: flash-style attention (no max subtraction, matches reference).
// Block = (bh, q-tile of 64). Streams K/V tiles of 64 through smem.
// S = (Q*0.125) @ K^T  -> exp -> rowsum accumulate -> O += P @ V.
// ---------------------------------------------------------------------------
#define ATTN_SMEM_BYTES ((4 * 64 * 72 + 64) * sizeof(float))

__global__ __launch_bounds__(256)
void attn_kernel(float* __restrict__ out)
{
    extern __shared__ float sm[];
    float* Qs = sm;                    // 64 x 72
    float* Ks = Qs + 64 * 72;          // 64 x 72
    float* Vs = Ks + 64 * 72;          // 64 x 72
    float* Ss = Vs + 64 * 72;          // 64 x 72 (scores / P / final O staging)
    float* rowsum = Ss + 64 * 72;      // 64

    const int bh = blockIdx.y;
    const int b  = bh >> 4;
    const int h  = bh & 15;
    const int q0 = blockIdx.x * 64;

    const float* Qp = g_Q + (size_t)bh * SEQ * DK;
    const float* Kp = g_K + (size_t)bh * SEQ * DK;
    const float* Vp = g_V + (size_t)bh * SEQ * DK;

    const int tid = threadIdx.x;
    const int warp = tid >> 5;
    const int wm = warp >> 2;
    const int wn = warp & 3;

    // Load Q tile, fold in 1/sqrt(64) scale
    #pragma unroll
    for (int it = 0; it < 4; it++) {
        int idx = tid + it * 256;      // 1024 float4 total
        int r = idx >> 4, c4 = idx & 15;
        float4 v = *reinterpret_cast<const float4*>(&Qp[(size_t)(q0 + r) * DK + c4 * 4]);
        v.x *= 0.125f; v.y *= 0.125f; v.z *= 0.125f; v.w *= 0.125f;
        *reinterpret_cast<float4*>(&Qs[r * 72 + c4 * 4]) = v;
    }
    if (tid < 64) rowsum[tid] = 0.0f;

    wmma::fragment<wmma::accumulator, 16, 16, 8, float> o_acc[2];
    wmma::fill_fragment(o_acc[0], 0.0f);
    wmma::fill_fragment(o_acc[1], 0.0f);

    for (int kt = 0; kt < SEQ / 64; kt++) {
        const int k0 = kt * 64;
        // Load K and V tiles
        #pragma unroll
        for (int it = 0; it < 4; it++) {
            int idx = tid + it * 256;
            int r = idx >> 4, c4 = idx & 15;
            *reinterpret_cast<float4*>(&Ks[r * 72 + c4 * 4]) =
                *reinterpret_cast<const float4*>(&Kp[(size_t)(k0 + r) * DK + c4 * 4]);
            *reinterpret_cast<float4*>(&Vs[r * 72 + c4 * 4]) =
                *reinterpret_cast<const float4*>(&Vp[(size_t)(k0 + r) * DK + c4 * 4]);
        }
        __syncthreads();

        // S = Qs @ Ks^T   (K tile is [key, d] row-major -> col_major B fragment)
        wmma::fragment<wmma::accumulator, 16, 16, 8, float> s_acc[2];
        wmma::fill_fragment(s_acc[0], 0.0f);
        wmma::fill_fragment(s_acc[1], 0.0f);
        #pragma unroll
        for (int kk = 0; kk < 8; kk++) {
            wmma::fragment<wmma::matrix_b, 16, 16, 8, wmma::precision::tf32, wmma::col_major> kb;
            wmma::load_matrix_sync(kb, &Ks[(wn * 16) * 72 + kk * 8], 72);
            #pragma unroll
            for (int t = 0; t < kb.num_elements; t++) kb.x[t] = wmma::__float_to_tf32(kb.x[t]);
            #pragma unroll
            for (int i = 0; i < 2; i++) {
                wmma::fragment<wmma::matrix_a, 16, 16, 8, wmma::precision::tf32, wmma::row_major> qa;
                wmma::load_matrix_sync(qa, &Qs[(wm * 32 + i * 16) * 72 + kk * 8], 72);
                #pragma unroll
                for (int t = 0; t < qa.num_elements; t++) qa.x[t] = wmma::__float_to_tf32(qa.x[t]);
                wmma::mma_sync(s_acc[i], qa, kb, s_acc[i]);
            }
        }
        wmma::store_matrix_sync(&Ss[(wm * 32 + 0) * 72 + wn * 16],  s_acc[0], 72, wmma::mem_row_major);
        wmma::store_matrix_sync(&Ss[(wm * 32 + 16) * 72 + wn * 16], s_acc[1], 72, wmma::mem_row_major);
        __syncthreads();

        // exp + rowsum partial (4 threads per row, 16 cols each)
        {
            int r = tid >> 2;
            int cbase = (tid & 3) * 16;
            float part = 0.0f;
            #pragma unroll
            for (int c = 0; c < 16; c++) {
                float p = __expf(Ss[r * 72 + cbase + c]);
                Ss[r * 72 + cbase + c] = p;
                part += p;
            }
            part += __shfl_xor_sync(0xffffffffu, part, 1);
            part += __shfl_xor_sync(0xffffffffu, part, 2);
            if ((tid & 3) == 0) rowsum[r] += part;
        }
        __syncthreads();

        // O += P @ V
        #pragma unroll
        for (int kk = 0; kk < 8; kk++) {
            wmma::fragment<wmma::matrix_b, 16, 16, 8, wmma::precision::tf32, wmma::row_major> vb;
            wmma::load_matrix_sync(vb, &Vs[(kk * 8) * 72 + wn * 16], 72);
            #pragma unroll
            for (int t = 0; t < vb.num_elements; t++) vb.x[t] = wmma::__float_to_tf32(vb.x[t]);
            #pragma unroll
            for (int i = 0; i < 2; i++) {
                wmma::fragment<wmma::matrix_a, 16, 16, 8, wmma::precision::tf32, wmma::row_major> pa;
                wmma::load_matrix_sync(pa, &Ss[(wm * 32 + i * 16) * 72 + kk * 8], 72);
                #pragma unroll
                for (int t = 0; t < pa.num_elements; t++) pa.x[t] = wmma::__float_to_tf32(pa.x[t]);
                wmma::mma_sync(o_acc[i], pa, vb, o_acc[i]);
            }
        }
        __syncthreads();
    }

    // Epilogue: normalize by rowsum and write [b, s, h*64 + d]
    wmma::store_matrix_sync(&Ss[(wm * 32 + 0) * 72 + wn * 16],  o_acc[0], 72, wmma::mem_row_major);
    wmma::store_matrix_sync(&Ss[(wm * 32 + 16) * 72 + wn * 16], o_acc[1], 72, wmma::mem_row_major);
    __syncthreads();

    {
        int r = tid >> 2;
        int cbase = (tid & 3) * 16;
        float inv = 1.0f / (rowsum[r] + 1e-8f);
        float* dst = out + ((size_t)(b * SEQ + q0 + r)) * DMODEL + h * DK;
        #pragma unroll
        for (int c = 0; c < 16; c++) {
            dst[cbase + c] = Ss[r * 72 + cbase + c] * inv;
        }
    }
}

// ---------------------------------------------------------------------------
extern "C" void kernel_launch(void* const* d_in, const int* in_sizes, int n_in,
                              void* d_out, int out_size)
{
    const float* x  = (const float*)d_in[0];
    const float* Wq = (const float*)d_in[1];
    const float* bq = (const float*)d_in[2];
    const float* Wk = (const float*)d_in[3];
    const float* bk = (const float*)d_in[4];
    const float* Wv = (const float*)d_in[5];
    const float* bv = (const float*)d_in[6];
    float* out = (float*)d_out;

    cudaFuncSetAttribute(attn_kernel, cudaFuncAttributeMaxDynamicSharedMemorySize,
                         (int)ATTN_SMEM_BYTES);

    dim3 gemm_grid(DMODEL / 64, MTOT / 64, 3);   // 16 x 64 x 3
    qkv_gemm_kernel<<<gemm_grid, 256>>>(x, Wq, bq, Wk, bk, Wv, bv);

    dim3 attn_grid(SEQ / 64, BH);                // 32 x 32
    attn_kernel<<<attn_grid, 256, ATTN_SMEM_BYTES>>>(out);
}

// round 2
// speedup vs baseline: 1.5923x; 1.5923x over previous
#include <cuda_runtime.h>
#include <cuda_bf16.h>
#include <mma.h>
#include <cstdint>

using namespace nvcuda;

// Problem constants
#define BATCH   2
#define SEQ     2048
#define DMODEL  1024
#define NHEADS  16
#define DK      64
#define BH      (BATCH * NHEADS)          // 32
#define MTOT    (BATCH * SEQ)             // 4096

// Scratch for Q, K, V in [b,h,s,d] layout (bh-major). Values are pre-rounded
// to tf32 (and Q pre-scaled by 1/sqrt(DK)) by the GEMM epilogue.
__device__ float g_Q[(size_t)BH * SEQ * DK];
__device__ float g_K[(size_t)BH * SEQ * DK];
__device__ float g_V[(size_t)BH * SEQ * DK];

// ---------------------------------------------------------------------------
// Helpers
// ---------------------------------------------------------------------------
__device__ __forceinline__ float to_tf32(float x) {
    uint32_t u;
    asm("cvt.rna.tf32.f32 %0, %1;" : "=r"(u) : "f"(x));
    return __uint_as_float(u);
}

__device__ __forceinline__ void mma_tf32(float c[4], const uint32_t a[4],
                                         uint32_t b0, uint32_t b1) {
    asm volatile(
        "mma.sync.aligned.m16n8k8.row.col.f32.tf32.tf32.f32 "
        "{%0,%1,%2,%3}, {%4,%5,%6,%7}, {%8,%9}, {%0,%1,%2,%3};"
        : "+f"(c[0]), "+f"(c[1]), "+f"(c[2]), "+f"(c[3])
        : "r"(a[0]), "r"(a[1]), "r"(a[2]), "r"(a[3]), "r"(b0), "r"(b1));
}

__device__ __forceinline__ void cp16(void* s, const void* gp) {
    uint32_t sa = (uint32_t)__cvta_generic_to_shared(s);
    asm volatile("cp.async.ca.shared.global [%0], [%1], 16;" :: "r"(sa), "l"(gp));
}
__device__ __forceinline__ void cp_commit() {
    asm volatile("cp.async.commit_group;");
}
__device__ __forceinline__ void cp_wait_all() {
    asm volatile("cp.async.wait_group 0;");
}

// ---------------------------------------------------------------------------
// Kernel 1: QKV projection GEMMs.  out[m,n] = sum_k X[m,k] * W[k,n] + b[n]
// Tile 64x64, BK=32, tf32 WMMA, 256 threads. Epilogue scatters into
// [bh, s, d] scratch, rounding to tf32 (Q additionally scaled by 0.125).
// ---------------------------------------------------------------------------
__global__ __launch_bounds__(256)
void qkv_gemm_kernel(const float* __restrict__ X,
                     const float* __restrict__ Wq, const float* __restrict__ bq,
                     const float* __restrict__ Wk, const float* __restrict__ bk,
                     const float* __restrict__ Wv, const float* __restrict__ bv)
{
    const float* W;
    const float* bias;
    float* Out;
    if (blockIdx.z == 0)      { W = Wq; bias = bq; Out = g_Q; }
    else if (blockIdx.z == 1) { W = Wk; bias = bk; Out = g_K; }
    else                      { W = Wv; bias = bv; Out = g_V; }

    __shared__ float As[64][36];
    __shared__ float Bs[32][72];
    __shared__ float Cs[64][68];

    const int m0  = blockIdx.y * 64;
    const int n0  = blockIdx.x * 64;
    const int tid = threadIdx.x;
    const int warp = tid >> 5;
    const int wm = warp >> 2;
    const int wn = warp & 3;

    wmma::fragment<wmma::accumulator, 16, 16, 8, float> acc[2];
    wmma::fill_fragment(acc[0], 0.0f);
    wmma::fill_fragment(acc[1], 0.0f);

    for (int k0 = 0; k0 < DMODEL; k0 += 32) {
        #pragma unroll
        for (int it = 0; it < 2; it++) {
            int idx = tid + it * 256;
            int r = idx >> 3, c4 = idx & 7;
            float4 v = *reinterpret_cast<const float4*>(&X[(size_t)(m0 + r) * DMODEL + k0 + c4 * 4]);
            *reinterpret_cast<float4*>(&As[r][c4 * 4]) = v;
        }
        #pragma unroll
        for (int it = 0; it < 2; it++) {
            int idx = tid + it * 256;
            int r = idx >> 4, c4 = idx & 15;
            float4 v = *reinterpret_cast<const float4*>(&W[(size_t)(k0 + r) * DMODEL + n0 + c4 * 4]);
            *reinterpret_cast<float4*>(&Bs[r][c4 * 4]) = v;
        }
        __syncthreads();

        #pragma unroll
        for (int kk = 0; kk < 4; kk++) {
            wmma::fragment<wmma::matrix_b, 16, 16, 8, wmma::precision::tf32, wmma::row_major> bf;
            wmma::load_matrix_sync(bf, &Bs[kk * 8][wn * 16], 72);
            #pragma unroll
            for (int t = 0; t < bf.num_elements; t++) bf.x[t] = wmma::__float_to_tf32(bf.x[t]);
            #pragma unroll
            for (int i = 0; i < 2; i++) {
                wmma::fragment<wmma::matrix_a, 16, 16, 8, wmma::precision::tf32, wmma::row_major> af;
                wmma::load_matrix_sync(af, &As[wm * 32 + i * 16][kk * 8], 36);
                #pragma unroll
                for (int t = 0; t < af.num_elements; t++) af.x[t] = wmma::__float_to_tf32(af.x[t]);
                wmma::mma_sync(acc[i], af, bf, acc[i]);
            }
        }
        __syncthreads();
    }

    wmma::store_matrix_sync(&Cs[wm * 32 + 0][wn * 16],  acc[0], 68, wmma::mem_row_major);
    wmma::store_matrix_sync(&Cs[wm * 32 + 16][wn * 16], acc[1], 68, wmma::mem_row_major);
    __syncthreads();

    const int b  = m0 / SEQ;
    const int s0 = m0 % SEQ;
    const int h  = n0 / DK;
    float* dst = Out + ((size_t)(b * NHEADS + h) * SEQ + s0) * DK;

    const bool isQ = (blockIdx.z == 0);
    for (int idx = tid; idx < 64 * 64; idx += 256) {
        int r = idx >> 6, c = idx & 63;
        float v = Cs[r][c] + bias[n0 + c];
        if (isQ) v *= 0.125f;                 // fold 1/sqrt(DK) into Q
        dst[(size_t)r * DK + c] = to_tf32(v); // pre-round for raw mma consumption
    }
}

// ---------------------------------------------------------------------------
// Kernel 2: flash-style attention with raw m16n8k8 tf32 mma.
// Block = 256 threads (8 warps), Q-tile 64 rows, K/V tiles of 64 streamed
// with cp.async double buffering. Q lives in registers across all K-tiles,
// exp on accumulator registers, rowsum in registers (one final reduction).
// Warp grid: 4 (rows) x 2 (cols); each warp does 16 rows x 32 cols.
// ---------------------------------------------------------------------------
#define KSTR 68
#define VSTR 72
#define PSTR 68
#define NKT  (SEQ / 64)

#define ATTN_SMEM_FLOATS (2*64*KSTR + 2*64*VSTR + 64*PSTR + 2*64)
#define ATTN_SMEM_BYTES  (ATTN_SMEM_FLOATS * sizeof(float))

__global__ __launch_bounds__(256)
void attn_kernel(float* __restrict__ out)
{
    extern __shared__ float sm[];
    float* Ks   = sm;                       // 2 bufs of 64 x KSTR
    float* Vs   = Ks + 2 * 64 * KSTR;       // 2 bufs of 64 x VSTR
    float* Ps   = Vs + 2 * 64 * VSTR;       // 64 x PSTR (Q staging, then P)
    float* rsum = Ps + 64 * PSTR;           // [2][64] per-column-half rowsums

    const int bh = blockIdx.y;
    const int b  = bh >> 4;
    const int h  = bh & 15;
    const int q0 = blockIdx.x * 64;

    const float* Qp = g_Q + (size_t)bh * SEQ * DK + (size_t)q0 * DK;
    const float* Kp = g_K + (size_t)bh * SEQ * DK;
    const float* Vp = g_V + (size_t)bh * SEQ * DK;

    const int tid  = threadIdx.x;
    const int lane = tid & 31;
    const int warp = tid >> 5;
    const int g = lane >> 2;      // groupID (0..7)
    const int t = lane & 3;       // threadID_in_group (0..3)
    const int wm = warp >> 1;     // 0..3  -> rows 16*wm
    const int wn = warp & 1;      // 0..1  -> cols 32*wn
    const int row0 = wm * 16;

    // Prefetch K/V tile 0
    {
        const float* kp = Kp;
        const float* vp = Vp;
        #pragma unroll
        for (int it = 0; it < 4; it++) {
            int idx = tid + it * 256;
            int r = idx >> 4, c4 = (idx & 15) * 4;
            cp16(&Ks[r * KSTR + c4], kp + (size_t)r * DK + c4);
            cp16(&Vs[r * VSTR + c4], vp + (size_t)r * DK + c4);
        }
        cp_commit();
    }

    // Stage Q into Ps, then load Q fragments into registers (stay resident)
    #pragma unroll
    for (int it = 0; it < 4; it++) {
        int idx = tid + it * 256;
        int r = idx >> 4, c4 = (idx & 15) * 4;
        *reinterpret_cast<float4*>(&Ps[r * PSTR + c4]) =
            *reinterpret_cast<const float4*>(&Qp[(size_t)r * DK + c4]);
    }
    __syncthreads();

    uint32_t qf[8][4];
    #pragma unroll
    for (int ks = 0; ks < 8; ks++) {
        qf[ks][0] = __float_as_uint(Ps[(row0 + g)     * PSTR + 8 * ks + t]);
        qf[ks][1] = __float_as_uint(Ps[(row0 + g + 8) * PSTR + 8 * ks + t]);
        qf[ks][2] = __float_as_uint(Ps[(row0 + g)     * PSTR + 8 * ks + t + 4]);
        qf[ks][3] = __float_as_uint(Ps[(row0 + g + 8) * PSTR + 8 * ks + t + 4]);
    }

    float oacc[4][4];
    #pragma unroll
    for (int j = 0; j < 4; j++)
        #pragma unroll
        for (int e = 0; e < 4; e++) oacc[j][e] = 0.0f;
    float rs0 = 0.0f, rs1 = 0.0f;

    for (int kt = 0; kt < NKT; kt++) {
        const int buf = kt & 1;
        cp_wait_all();
        __syncthreads();   // data ready for all; prior PV reads done; qf reads done

        // Prefetch next tile into the other buffer
        if (kt + 1 < NKT) {
            const float* kp = Kp + (size_t)(kt + 1) * 64 * DK;
            const float* vp = Vp + (size_t)(kt + 1) * 64 * DK;
            float* Kn = Ks + (buf ^ 1) * 64 * KSTR;
            float* Vn = Vs + (buf ^ 1) * 64 * VSTR;
            #pragma unroll
            for (int it = 0; it < 4; it++) {
                int idx = tid + it * 256;
                int r = idx >> 4, c4 = (idx & 15) * 4;
                cp16(&Kn[r * KSTR + c4], kp + (size_t)r * DK + c4);
                cp16(&Vn[r * VSTR + c4], vp + (size_t)r * DK + c4);
            }
            cp_commit();
        }

        const float* Kb = Ks + buf * 64 * KSTR;
        const float* Vb = Vs + buf * 64 * VSTR;

        // S = Q @ K^T  (Q in regs, K fragments from smem — conflict-free)
        float sacc[4][4];
        #pragma unroll
        for (int j = 0; j < 4; j++)
            #pragma unroll
            for (int e = 0; e < 4; e++) sacc[j][e] = 0.0f;

        #pragma unroll
        for (int ks = 0; ks < 8; ks++) {
            #pragma unroll
            for (int j = 0; j < 4; j++) {
                int key = wn * 32 + j * 8 + g;
                uint32_t b0 = __float_as_uint(Kb[key * KSTR + 8 * ks + t]);
                uint32_t b1 = __float_as_uint(Kb[key * KSTR + 8 * ks + t + 4]);
                mma_tf32(sacc[j], qf[ks], b0, b1);
            }
        }

        // exp on registers, accumulate rowsums, store P (tf32-rounded) to smem
        #pragma unroll
        for (int j = 0; j < 4; j++) {
            int scol = wn * 32 + j * 8 + 2 * t;
            float e0 = __expf(sacc[j][0]);
            float e1 = __expf(sacc[j][1]);
            float e2 = __expf(sacc[j][2]);
            float e3 = __expf(sacc[j][3]);
            rs0 += e0 + e1;
            rs1 += e2 + e3;
            float2 p01 = make_float2(to_tf32(e0), to_tf32(e1));
            float2 p23 = make_float2(to_tf32(e2), to_tf32(e3));
            *reinterpret_cast<float2*>(&Ps[(row0 + g)     * PSTR + scol]) = p01;
            *reinterpret_cast<float2*>(&Ps[(row0 + g + 8) * PSTR + scol]) = p23;
        }
        __syncthreads();   // P visible to all warps

        // O += P @ V  (A from Ps, B from Vs — both conflict-free strides)
        #pragma unroll
        for (int ks = 0; ks < 8; ks++) {
            uint32_t a[4];
            a[0] = __float_as_uint(Ps[(row0 + g)     * PSTR + 8 * ks + t]);
            a[1] = __float_as_uint(Ps[(row0 + g + 8) * PSTR + 8 * ks + t]);
            a[2] = __float_as_uint(Ps[(row0 + g)     * PSTR + 8 * ks + t + 4]);
            a[3] = __float_as_uint(Ps[(row0 + g + 8) * PSTR + 8 * ks + t + 4]);
            #pragma unroll
            for (int j = 0; j < 4; j++) {
                int dcol = wn * 32 + j * 8 + g;
                uint32_t b0 = __float_as_uint(Vb[(8 * ks + t)     * VSTR + dcol]);
                uint32_t b1 = __float_as_uint(Vb[(8 * ks + t + 4) * VSTR + dcol]);
                mma_tf32(oacc[j], a, b0, b1);
            }
        }
        // next iteration's post-wait __syncthreads protects Ps/Vb reuse
    }

    // Final rowsum reduction: quad shuffle, then combine the two column halves
    rs0 += __shfl_xor_sync(0xffffffffu, rs0, 1);
    rs0 += __shfl_xor_sync(0xffffffffu, rs0, 2);
    rs1 += __shfl_xor_sync(0xffffffffu, rs1, 1);
    rs1 += __shfl_xor_sync(0xffffffffu, rs1, 2);
    __syncthreads();   // all PV reads complete before reusing nothing; ensures rsum ordering below
    if (t == 0) {
        rsum[wn * 64 + row0 + g]     = rs0;
        rsum[wn * 64 + row0 + g + 8] = rs1;
    }
    __syncthreads();

    float inv0 = 1.0f / (rsum[row0 + g]     + rsum[64 + row0 + g]     + 1e-8f);
    float inv1 = 1.0f / (rsum[row0 + g + 8] + rsum[64 + row0 + g + 8] + 1e-8f);

    // Write O: out[b, q0+row, h*64 + col]
    #pragma unroll
    for (int j = 0; j < 4; j++) {
        int dcol = wn * 32 + j * 8 + 2 * t;
        float* dst0 = out + ((size_t)(b * SEQ + q0 + row0 + g)) * DMODEL + h * DK + dcol;
        float* dst1 = dst0 + (size_t)8 * DMODEL;
        *reinterpret_cast<float2*>(dst0) = make_float2(oacc[j][0] * inv0, oacc[j][1] * inv0);
        *reinterpret_cast<float2*>(dst1) = make_float2(oacc[j][2] * inv1, oacc[j][3] * inv1);
    }
}

// ---------------------------------------------------------------------------
extern "C" void kernel_launch(void* const* d_in, const int* in_sizes, int n_in,
                              void* d_out, int out_size)
{
    const float* x  = (const float*)d_in[0];
    const float* Wq = (const float*)d_in[1];
    const float* bq = (const float*)d_in[2];
    const float* Wk = (const float*)d_in[3];
    const float* bk = (const float*)d_in[4];
    const float* Wv = (const float*)d_in[5];
    const float* bv = (const float*)d_in[6];
    float* out = (float*)d_out;

    cudaFuncSetAttribute(attn_kernel, cudaFuncAttributeMaxDynamicSharedMemorySize,
                         (int)ATTN_SMEM_BYTES);

    dim3 gemm_grid(DMODEL / 64, MTOT / 64, 3);   // 16 x 64 x 3
    qkv_gemm_kernel<<<gemm_grid, 256>>>(x, Wq, bq, Wk, bk, Wv, bv);

    dim3 attn_grid(SEQ / 64, BH);                // 32 x 32
    attn_kernel<<<attn_grid, 256, ATTN_SMEM_BYTES>>>(out);
}

// round 3
// speedup vs baseline: 2.3953x; 1.5043x over previous
#include <cuda_runtime.h>
#include <cuda_bf16.h>
#include <cstdint>

// Problem constants
#define BATCH   2
#define SEQ     2048
#define DMODEL  1024
#define NHEADS  16
#define DK      64
#define BH      (BATCH * NHEADS)          // 32
#define MTOT    (BATCH * SEQ)             // 4096

// Scratch: tf32-pre-rounded copies of X and W, and projected Q/K/V
__device__ float g_X[(size_t)MTOT * DMODEL];
__device__ float g_W[(size_t)3 * DMODEL * DMODEL];
__device__ float g_Q[(size_t)BH * SEQ * DK];
__device__ float g_K[(size_t)BH * SEQ * DK];
__device__ float g_V[(size_t)BH * SEQ * DK];

// ---------------------------------------------------------------------------
// Helpers
// ---------------------------------------------------------------------------
__device__ __forceinline__ float to_tf32(float x) {
    uint32_t u;
    asm("cvt.rna.tf32.f32 %0, %1;" : "=r"(u) : "f"(x));
    return __uint_as_float(u);
}

__device__ __forceinline__ void mma_tf32(float c[4], const uint32_t a[4],
                                         uint32_t b0, uint32_t b1) {
    asm volatile(
        "mma.sync.aligned.m16n8k8.row.col.f32.tf32.tf32.f32 "
        "{%0,%1,%2,%3}, {%4,%5,%6,%7}, {%8,%9}, {%0,%1,%2,%3};"
        : "+f"(c[0]), "+f"(c[1]), "+f"(c[2]), "+f"(c[3])
        : "r"(a[0]), "r"(a[1]), "r"(a[2]), "r"(a[3]), "r"(b0), "r"(b1));
}

__device__ __forceinline__ void cp16(void* s, const void* gp) {
    uint32_t sa = (uint32_t)__cvta_generic_to_shared(s);
    asm volatile("cp.async.ca.shared.global [%0], [%1], 16;" :: "r"(sa), "l"(gp));
}
__device__ __forceinline__ void cp_commit() {
    asm volatile("cp.async.commit_group;");
}
__device__ __forceinline__ void cp_wait_all() {
    asm volatile("cp.async.wait_group 0;");
}

// ---------------------------------------------------------------------------
// Kernel 0: elementwise tf32 pre-round (float4 vectorized)
// ---------------------------------------------------------------------------
__global__ void round_copy(const float* __restrict__ src, float* __restrict__ dst, int n4)
{
    int i = blockIdx.x * blockDim.x + threadIdx.x;
    if (i < n4) {
        float4 v = reinterpret_cast<const float4*>(src)[i];
        v.x = to_tf32(v.x); v.y = to_tf32(v.y);
        v.z = to_tf32(v.z); v.w = to_tf32(v.w);
        reinterpret_cast<float4*>(dst)[i] = v;
    }
}

// ---------------------------------------------------------------------------
// Kernel 1: QKV projection GEMM. out[m,n] = sum_k X[m,k]*W[k,n] + b[n]
// BM=128, BN=64, BK=32, raw m16n8k8 tf32 mma, cp.async double buffer.
// Inputs pre-rounded to tf32 -> zero converts in the loop.
// 8 warps as 4x2; each warp computes 32x32. Register epilogue scatters
// into [bh,s,d] scratch with bias (+0.125 scale for Q) + tf32 round.
// ---------------------------------------------------------------------------
#define BM 128
#define BN 64
#define BK 32
#define ASTR 36
#define BSTR 72
#define GEMM_SMEM_FLOATS (2 * BM * ASTR + 2 * BK * BSTR)
#define GEMM_SMEM_BYTES  (GEMM_SMEM_FLOATS * sizeof(float))
#define NKTILES (DMODEL / BK)

__global__ __launch_bounds__(256)
void qkv_gemm_kernel(const float* __restrict__ bq,
                     const float* __restrict__ bk,
                     const float* __restrict__ bv)
{
    extern __shared__ float sg[];
    float* As = sg;                        // 2 bufs of BM x ASTR
    float* Bs = sg + 2 * BM * ASTR;        // 2 bufs of BK x BSTR

    const float* W;
    const float* bias;
    float* Out;
    if (blockIdx.z == 0)      { W = g_W;                              bias = bq; Out = g_Q; }
    else if (blockIdx.z == 1) { W = g_W + (size_t)DMODEL * DMODEL;    bias = bk; Out = g_K; }
    else                      { W = g_W + (size_t)2 * DMODEL * DMODEL; bias = bv; Out = g_V; }

    const int m0 = blockIdx.y * BM;
    const int n0 = blockIdx.x * BN;
    const int tid  = threadIdx.x;
    const int lane = tid & 31;
    const int warp = tid >> 5;
    const int g = lane >> 2;
    const int t = lane & 3;
    const int wm = warp >> 1;     // 0..3
    const int wn = warp & 1;      // 0..1

    const float* Xp = g_X + (size_t)m0 * DMODEL;

    // Prefetch tile 0
    {
        #pragma unroll
        for (int it = 0; it < 4; it++) {     // A: 128 x 32 = 1024 float4
            int idx = tid + it * 256;
            int r = idx >> 3, c4 = (idx & 7) * 4;
            cp16(&As[r * ASTR + c4], Xp + (size_t)r * DMODEL + c4);
        }
        #pragma unroll
        for (int it = 0; it < 2; it++) {     // B: 32 x 64 = 512 float4
            int idx = tid + it * 256;
            int r = idx >> 4, c4 = (idx & 15) * 4;
            cp16(&Bs[r * BSTR + c4], W + (size_t)r * DMODEL + n0 + c4);
        }
        cp_commit();
    }

    float acc[2][4][4];
    #pragma unroll
    for (int fm = 0; fm < 2; fm++)
        #pragma unroll
        for (int fn = 0; fn < 4; fn++)
            #pragma unroll
            for (int e = 0; e < 4; e++) acc[fm][fn][e] = 0.0f;

    for (int kt = 0; kt < NKTILES; kt++) {
        const int buf = kt & 1;
        cp_wait_all();
        __syncthreads();

        if (kt + 1 < NKTILES) {
            const int k0n = (kt + 1) * BK;
            float* An = As + (buf ^ 1) * BM * ASTR;
            float* Bn = Bs + (buf ^ 1) * BK * BSTR;
            #pragma unroll
            for (int it = 0; it < 4; it++) {
                int idx = tid + it * 256;
                int r = idx >> 3, c4 = (idx & 7) * 4;
                cp16(&An[r * ASTR + c4], Xp + (size_t)r * DMODEL + k0n + c4);
            }
            #pragma unroll
            for (int it = 0; it < 2; it++) {
                int idx = tid + it * 256;
                int r = idx >> 4, c4 = (idx & 15) * 4;
                cp16(&Bn[r * BSTR + c4], W + (size_t)(k0n + r) * DMODEL + n0 + c4);
            }
            cp_commit();
        }

        const float* Ab = As + buf * BM * ASTR;
        const float* Bb = Bs + buf * BK * BSTR;

        #pragma unroll
        for (int ks = 0; ks < 4; ks++) {
            uint32_t a[2][4];
            #pragma unroll
            for (int fm = 0; fm < 2; fm++) {
                int rb = wm * 32 + fm * 16;
                a[fm][0] = __float_as_uint(Ab[(rb + g)     * ASTR + 8 * ks + t]);
                a[fm][1] = __float_as_uint(Ab[(rb + g + 8) * ASTR + 8 * ks + t]);
                a[fm][2] = __float_as_uint(Ab[(rb + g)     * ASTR + 8 * ks + t + 4]);
                a[fm][3] = __float_as_uint(Ab[(rb + g + 8) * ASTR + 8 * ks + t + 4]);
            }
            #pragma unroll
            for (int fn = 0; fn < 4; fn++) {
                int col = wn * 32 + fn * 8 + g;
                uint32_t b0 = __float_as_uint(Bb[(8 * ks + t)     * BSTR + col]);
                uint32_t b1 = __float_as_uint(Bb[(8 * ks + t + 4) * BSTR + col]);
                mma_tf32(acc[0][fn], a[0], b0, b1);
                mma_tf32(acc[1][fn], a[1], b0, b1);
            }
        }
    }

    // Register epilogue: bias (+ Q scale) + tf32 round, scatter to [bh,s,d]
    const int b  = m0 / SEQ;              // BM divides SEQ
    const int s0 = m0 % SEQ;
    const int h  = blockIdx.x;            // BN == DK
    const float scale = (blockIdx.z == 0) ? 0.125f : 1.0f;
    float* dstbase = Out + ((size_t)(b * NHEADS + h) * SEQ + s0) * DK;

    #pragma unroll
    for (int fm = 0; fm < 2; fm++) {
        int r0 = wm * 32 + fm * 16 + g;
        #pragma unroll
        for (int fn = 0; fn < 4; fn++) {
            int c = wn * 32 + fn * 8 + 2 * t;
            float bv0 = bias[n0 + c];
            float bv1 = bias[n0 + c + 1];
            float2 v0 = make_float2(to_tf32((acc[fm][fn][0] + bv0) * scale),
                                    to_tf32((acc[fm][fn][1] + bv1) * scale));
            float2 v1 = make_float2(to_tf32((acc[fm][fn][2] + bv0) * scale),
                                    to_tf32((acc[fm][fn][3] + bv1) * scale));
            *reinterpret_cast<float2*>(&dstbase[(size_t)(r0)     * DK + c]) = v0;
            *reinterpret_cast<float2*>(&dstbase[(size_t)(r0 + 8) * DK + c]) = v1;
        }
    }
}

// ---------------------------------------------------------------------------
// Kernel 2: flash-style attention with raw m16n8k8 tf32 mma (unchanged R2).
// ---------------------------------------------------------------------------
#define KSTR 68
#define VSTR 72
#define PSTR 68
#define NKT  (SEQ / 64)

#define ATTN_SMEM_FLOATS (2*64*KSTR + 2*64*VSTR + 64*PSTR + 2*64)
#define ATTN_SMEM_BYTES  (ATTN_SMEM_FLOATS * sizeof(float))

__global__ __launch_bounds__(256)
void attn_kernel(float* __restrict__ out)
{
    extern __shared__ float sm[];
    float* Ks   = sm;                       // 2 bufs of 64 x KSTR
    float* Vs   = Ks + 2 * 64 * KSTR;       // 2 bufs of 64 x VSTR
    float* Ps   = Vs + 2 * 64 * VSTR;       // 64 x PSTR (Q staging, then P)
    float* rsum = Ps + 64 * PSTR;           // [2][64]

    const int bh = blockIdx.y;
    const int b  = bh >> 4;
    const int h  = bh & 15;
    const int q0 = blockIdx.x * 64;

    const float* Qp = g_Q + (size_t)bh * SEQ * DK + (size_t)q0 * DK;
    const float* Kp = g_K + (size_t)bh * SEQ * DK;
    const float* Vp = g_V + (size_t)bh * SEQ * DK;

    const int tid  = threadIdx.x;
    const int lane = tid & 31;
    const int warp = tid >> 5;
    const int g = lane >> 2;
    const int t = lane & 3;
    const int wm = warp >> 1;
    const int wn = warp & 1;
    const int row0 = wm * 16;

    {
        const float* kp = Kp;
        const float* vp = Vp;
        #pragma unroll
        for (int it = 0; it < 4; it++) {
            int idx = tid + it * 256;
            int r = idx >> 4, c4 = (idx & 15) * 4;
            cp16(&Ks[r * KSTR + c4], kp + (size_t)r * DK + c4);
            cp16(&Vs[r * VSTR + c4], vp + (size_t)r * DK + c4);
        }
        cp_commit();
    }

    #pragma unroll
    for (int it = 0; it < 4; it++) {
        int idx = tid + it * 256;
        int r = idx >> 4, c4 = (idx & 15) * 4;
        *reinterpret_cast<float4*>(&Ps[r * PSTR + c4]) =
            *reinterpret_cast<const float4*>(&Qp[(size_t)r * DK + c4]);
    }
    __syncthreads();

    uint32_t qf[8][4];
    #pragma unroll
    for (int ks = 0; ks < 8; ks++) {
        qf[ks][0] = __float_as_uint(Ps[(row0 + g)     * PSTR + 8 * ks + t]);
        qf[ks][1] = __float_as_uint(Ps[(row0 + g + 8) * PSTR + 8 * ks + t]);
        qf[ks][2] = __float_as_uint(Ps[(row0 + g)     * PSTR + 8 * ks + t + 4]);
        qf[ks][3] = __float_as_uint(Ps[(row0 + g + 8) * PSTR + 8 * ks + t + 4]);
    }

    float oacc[4][4];
    #pragma unroll
    for (int j = 0; j < 4; j++)
        #pragma unroll
        for (int e = 0; e < 4; e++) oacc[j][e] = 0.0f;
    float rs0 = 0.0f, rs1 = 0.0f;

    for (int kt = 0; kt < NKT; kt++) {
        const int buf = kt & 1;
        cp_wait_all();
        __syncthreads();

        if (kt + 1 < NKT) {
            const float* kp = Kp + (size_t)(kt + 1) * 64 * DK;
            const float* vp = Vp + (size_t)(kt + 1) * 64 * DK;
            float* Kn = Ks + (buf ^ 1) * 64 * KSTR;
            float* Vn = Vs + (buf ^ 1) * 64 * VSTR;
            #pragma unroll
            for (int it = 0; it < 4; it++) {
                int idx = tid + it * 256;
                int r = idx >> 4, c4 = (idx & 15) * 4;
                cp16(&Kn[r * KSTR + c4], kp + (size_t)r * DK + c4);
                cp16(&Vn[r * VSTR + c4], vp + (size_t)r * DK + c4);
            }
            cp_commit();
        }

        const float* Kb = Ks + buf * 64 * KSTR;
        const float* Vb = Vs + buf * 64 * VSTR;

        float sacc[4][4];
        #pragma unroll
        for (int j = 0; j < 4; j++)
            #pragma unroll
            for (int e = 0; e < 4; e++) sacc[j][e] = 0.0f;

        #pragma unroll
        for (int ks = 0; ks < 8; ks++) {
            #pragma unroll
            for (int j = 0; j < 4; j++) {
                int key = wn * 32 + j * 8 + g;
                uint32_t b0 = __float_as_uint(Kb[key * KSTR + 8 * ks + t]);
                uint32_t b1 = __float_as_uint(Kb[key * KSTR + 8 * ks + t + 4]);
                mma_tf32(sacc[j], qf[ks], b0, b1);
            }
        }

        #pragma unroll
        for (int j = 0; j < 4; j++) {
            int scol = wn * 32 + j * 8 + 2 * t;
            float e0 = __expf(sacc[j][0]);
            float e1 = __expf(sacc[j][1]);
            float e2 = __expf(sacc[j][2]);
            float e3 = __expf(sacc[j][3]);
            rs0 += e0 + e1;
            rs1 += e2 + e3;
            float2 p01 = make_float2(to_tf32(e0), to_tf32(e1));
            float2 p23 = make_float2(to_tf32(e2), to_tf32(e3));
            *reinterpret_cast<float2*>(&Ps[(row0 + g)     * PSTR + scol]) = p01;
            *reinterpret_cast<float2*>(&Ps[(row0 + g + 8) * PSTR + scol]) = p23;
        }
        __syncthreads();

        #pragma unroll
        for (int ks = 0; ks < 8; ks++) {
            uint32_t a[4];
            a[0] = __float_as_uint(Ps[(row0 + g)     * PSTR + 8 * ks + t]);
            a[1] = __float_as_uint(Ps[(row0 + g + 8) * PSTR + 8 * ks + t]);
            a[2] = __float_as_uint(Ps[(row0 + g)     * PSTR + 8 * ks + t + 4]);
            a[3] = __float_as_uint(Ps[(row0 + g + 8) * PSTR + 8 * ks + t + 4]);
            #pragma unroll
            for (int j = 0; j < 4; j++) {
                int dcol = wn * 32 + j * 8 + g;
                uint32_t b0 = __float_as_uint(Vb[(8 * ks + t)     * VSTR + dcol]);
                uint32_t b1 = __float_as_uint(Vb[(8 * ks + t + 4) * VSTR + dcol]);
                mma_tf32(oacc[j], a, b0, b1);
            }
        }
    }

    rs0 += __shfl_xor_sync(0xffffffffu, rs0, 1);
    rs0 += __shfl_xor_sync(0xffffffffu, rs0, 2);
    rs1 += __shfl_xor_sync(0xffffffffu, rs1, 1);
    rs1 += __shfl_xor_sync(0xffffffffu, rs1, 2);
    __syncthreads();
    if (t == 0) {
        rsum[wn * 64 + row0 + g]     = rs0;
        rsum[wn * 64 + row0 + g + 8] = rs1;
    }
    __syncthreads();

    float inv0 = 1.0f / (rsum[row0 + g]     + rsum[64 + row0 + g]     + 1e-8f);
    float inv1 = 1.0f / (rsum[row0 + g + 8] + rsum[64 + row0 + g + 8] + 1e-8f);

    #pragma unroll
    for (int j = 0; j < 4; j++) {
        int dcol = wn * 32 + j * 8 + 2 * t;
        float* dst0 = out + ((size_t)(b * SEQ + q0 + row0 + g)) * DMODEL + h * DK + dcol;
        float* dst1 = dst0 + (size_t)8 * DMODEL;
        *reinterpret_cast<float2*>(dst0) = make_float2(oacc[j][0] * inv0, oacc[j][1] * inv0);
        *reinterpret_cast<float2*>(dst1) = make_float2(oacc[j][2] * inv1, oacc[j][3] * inv1);
    }
}

// ---------------------------------------------------------------------------
extern "C" void kernel_launch(void* const* d_in, const int* in_sizes, int n_in,
                              void* d_out, int out_size)
{
    const float* x  = (const float*)d_in[0];
    const float* Wq = (const float*)d_in[1];
    const float* bq = (const float*)d_in[2];
    const float* Wk = (const float*)d_in[3];
    const float* bk = (const float*)d_in[4];
    const float* Wv = (const float*)d_in[5];
    const float* bv = (const float*)d_in[6];
    float* out = (float*)d_out;

    cudaFuncSetAttribute(attn_kernel, cudaFuncAttributeMaxDynamicSharedMemorySize,
                         (int)ATTN_SMEM_BYTES);
    cudaFuncSetAttribute(qkv_gemm_kernel, cudaFuncAttributeMaxDynamicSharedMemorySize,
                         (int)GEMM_SMEM_BYTES);

    // Pre-round X and W to tf32
    float* gx; cudaGetSymbolAddress((void**)&gx, g_X);
    float* gw; cudaGetSymbolAddress((void**)&gw, g_W);
    const int xn4 = MTOT * DMODEL / 4;
    const int wn4 = DMODEL * DMODEL / 4;
    round_copy<<<(xn4 + 255) / 256, 256>>>(x,  gx, xn4);
    round_copy<<<(wn4 + 255) / 256, 256>>>(Wq, gw, wn4);
    round_copy<<<(wn4 + 255) / 256, 256>>>(Wk, gw + (size_t)DMODEL * DMODEL, wn4);
    round_copy<<<(wn4 + 255) / 256, 256>>>(Wv, gw + (size_t)2 * DMODEL * DMODEL, wn4);

    dim3 gemm_grid(DMODEL / BN, MTOT / BM, 3);   // 16 x 32 x 3
    qkv_gemm_kernel<<<gemm_grid, 256, GEMM_SMEM_BYTES>>>(bq, bk, bv);

    dim3 attn_grid(SEQ / 64, BH);                // 32 x 32
    attn_kernel<<<attn_grid, 256, ATTN_SMEM_BYTES>>>(out);
}

// round 4
// speedup vs baseline: 2.6232x; 1.0951x over previous
#include <cuda_runtime.h>
#include <cuda_bf16.h>
#include <cstdint>

// Problem constants
#define BATCH   2
#define SEQ     2048
#define DMODEL  1024
#define NHEADS  16
#define DK      64
#define BH      (BATCH * NHEADS)          // 32
#define MTOT    (BATCH * SEQ)             // 4096

// Scratch: tf32-pre-rounded copies of X and W, and projected Q/K/V
__device__ float g_X[(size_t)MTOT * DMODEL];
__device__ float g_W[(size_t)3 * DMODEL * DMODEL];
__device__ float g_Q[(size_t)BH * SEQ * DK];
__device__ float g_K[(size_t)BH * SEQ * DK];
__device__ float g_V[(size_t)BH * SEQ * DK];

// ---------------------------------------------------------------------------
// Helpers
// ---------------------------------------------------------------------------
__device__ __forceinline__ float to_tf32(float x) {
    uint32_t u;
    asm("cvt.rna.tf32.f32 %0, %1;" : "=r"(u) : "f"(x));
    return __uint_as_float(u);
}

__device__ __forceinline__ void mma_tf32(float c[4], const uint32_t a[4],
                                         uint32_t b0, uint32_t b1) {
    asm volatile(
        "mma.sync.aligned.m16n8k8.row.col.f32.tf32.tf32.f32 "
        "{%0,%1,%2,%3}, {%4,%5,%6,%7}, {%8,%9}, {%0,%1,%2,%3};"
        : "+f"(c[0]), "+f"(c[1]), "+f"(c[2]), "+f"(c[3])
        : "r"(a[0]), "r"(a[1]), "r"(a[2]), "r"(a[3]), "r"(b0), "r"(b1));
}

__device__ __forceinline__ void cp16(void* s, const void* gp) {
    uint32_t sa = (uint32_t)__cvta_generic_to_shared(s);
    asm volatile("cp.async.ca.shared.global [%0], [%1], 16;" :: "r"(sa), "l"(gp));
}
__device__ __forceinline__ void cp_commit() {
    asm volatile("cp.async.commit_group;");
}
__device__ __forceinline__ void cp_wait_all() {
    asm volatile("cp.async.wait_group 0;");
}

// ---------------------------------------------------------------------------
// Kernel 0: elementwise tf32 pre-round (float4 vectorized)
// ---------------------------------------------------------------------------
__global__ void round_copy(const float* __restrict__ src, float* __restrict__ dst, int n4)
{
    int i = blockIdx.x * blockDim.x + threadIdx.x;
    if (i < n4) {
        float4 v = reinterpret_cast<const float4*>(src)[i];
        v.x = to_tf32(v.x); v.y = to_tf32(v.y);
        v.z = to_tf32(v.z); v.w = to_tf32(v.w);
        reinterpret_cast<float4*>(dst)[i] = v;
    }
}

// ---------------------------------------------------------------------------
// Kernel 1: QKV projection GEMM. out[m,n] = sum_k X[m,k]*W[k,n] + b[n]
// BM=128, BN=128, BK=32. Warp grid 2x4; warp tile 64x32 (fm=4, fn=4).
// cp.async double buffer, raw m16n8k8 tf32. Register epilogue scatters
// into [bh,s,d] scratch with bias (+0.125 for Q) + tf32 round.
// ---------------------------------------------------------------------------
#define BM 128
#define BN 128
#define BK 32
#define ASTR 36
#define BSTR 136
#define GEMM_SMEM_FLOATS (2 * BM * ASTR + 2 * BK * BSTR)
#define GEMM_SMEM_BYTES  (GEMM_SMEM_FLOATS * sizeof(float))
#define NKTILES (DMODEL / BK)

__global__ __launch_bounds__(256, 2)
void qkv_gemm_kernel(const float* __restrict__ bq,
                     const float* __restrict__ bk,
                     const float* __restrict__ bv)
{
    extern __shared__ float sg[];
    float* As = sg;                        // 2 bufs of BM x ASTR
    float* Bs = sg + 2 * BM * ASTR;        // 2 bufs of BK x BSTR

    const float* W;
    const float* bias;
    float* Out;
    if (blockIdx.z == 0)      { W = g_W;                               bias = bq; Out = g_Q; }
    else if (blockIdx.z == 1) { W = g_W + (size_t)DMODEL * DMODEL;     bias = bk; Out = g_K; }
    else                      { W = g_W + (size_t)2 * DMODEL * DMODEL; bias = bv; Out = g_V; }

    const int m0 = blockIdx.y * BM;
    const int n0 = blockIdx.x * BN;
    const int tid  = threadIdx.x;
    const int lane = tid & 31;
    const int warp = tid >> 5;
    const int g = lane >> 2;
    const int t = lane & 3;
    const int wm = warp >> 2;     // 0..1 -> rows 64*wm
    const int wn = warp & 3;      // 0..3 -> cols 32*wn

    const float* Xp = g_X + (size_t)m0 * DMODEL;

    // Prefetch tile 0
    {
        #pragma unroll
        for (int it = 0; it < 4; it++) {     // A: 128 x 32 = 1024 float4
            int idx = tid + it * 256;
            int r = idx >> 3, c4 = (idx & 7) * 4;
            cp16(&As[r * ASTR + c4], Xp + (size_t)r * DMODEL + c4);
        }
        #pragma unroll
        for (int it = 0; it < 4; it++) {     // B: 32 x 128 = 1024 float4
            int idx = tid + it * 256;
            int r = idx >> 5, c4 = (idx & 31) * 4;
            cp16(&Bs[r * BSTR + c4], W + (size_t)r * DMODEL + n0 + c4);
        }
        cp_commit();
    }

    float acc[4][4][4];
    #pragma unroll
    for (int fm = 0; fm < 4; fm++)
        #pragma unroll
        for (int fn = 0; fn < 4; fn++)
            #pragma unroll
            for (int e = 0; e < 4; e++) acc[fm][fn][e] = 0.0f;

    for (int kt = 0; kt < NKTILES; kt++) {
        const int buf = kt & 1;
        cp_wait_all();
        __syncthreads();

        if (kt + 1 < NKTILES) {
            const int k0n = (kt + 1) * BK;
            float* An = As + (buf ^ 1) * BM * ASTR;
            float* Bn = Bs + (buf ^ 1) * BK * BSTR;
            #pragma unroll
            for (int it = 0; it < 4; it++) {
                int idx = tid + it * 256;
                int r = idx >> 3, c4 = (idx & 7) * 4;
                cp16(&An[r * ASTR + c4], Xp + (size_t)r * DMODEL + k0n + c4);
            }
            #pragma unroll
            for (int it = 0; it < 4; it++) {
                int idx = tid + it * 256;
                int r = idx >> 5, c4 = (idx & 31) * 4;
                cp16(&Bn[r * BSTR + c4], W + (size_t)(k0n + r) * DMODEL + n0 + c4);
            }
            cp_commit();
        }

        const float* Ab = As + buf * BM * ASTR;
        const float* Bb = Bs + buf * BK * BSTR;

        #pragma unroll
        for (int ks = 0; ks < 4; ks++) {
            uint32_t a[4][4];
            #pragma unroll
            for (int fm = 0; fm < 4; fm++) {
                int rb = wm * 64 + fm * 16;
                a[fm][0] = __float_as_uint(Ab[(rb + g)     * ASTR + 8 * ks + t]);
                a[fm][1] = __float_as_uint(Ab[(rb + g + 8) * ASTR + 8 * ks + t]);
                a[fm][2] = __float_as_uint(Ab[(rb + g)     * ASTR + 8 * ks + t + 4]);
                a[fm][3] = __float_as_uint(Ab[(rb + g + 8) * ASTR + 8 * ks + t + 4]);
            }
            #pragma unroll
            for (int fn = 0; fn < 4; fn++) {
                int col = wn * 32 + fn * 8 + g;
                uint32_t b0 = __float_as_uint(Bb[(8 * ks + t)     * BSTR + col]);
                uint32_t b1 = __float_as_uint(Bb[(8 * ks + t + 4) * BSTR + col]);
                #pragma unroll
                for (int fm = 0; fm < 4; fm++) mma_tf32(acc[fm][fn], a[fm], b0, b1);
            }
        }
    }

    // Register epilogue: bias (+ Q scale) + tf32 round, scatter to [bh,s,d]
    const int b  = m0 / SEQ;
    const int s0 = m0 % SEQ;
    const int h0 = n0 >> 6;               // BN=128 spans 2 heads
    const float scale = (blockIdx.z == 0) ? 0.125f : 1.0f;

    #pragma unroll
    for (int fm = 0; fm < 4; fm++) {
        int r0 = wm * 64 + fm * 16 + g;
        #pragma unroll
        for (int fn = 0; fn < 4; fn++) {
            int c = wn * 32 + fn * 8 + 2 * t;
            int h = h0 + (c >> 6);
            int cc = c & 63;
            float bv0 = bias[n0 + c];
            float bv1 = bias[n0 + c + 1];
            float* dstbase = Out + ((size_t)(b * NHEADS + h) * SEQ + s0) * DK + cc;
            float2 v0 = make_float2(to_tf32((acc[fm][fn][0] + bv0) * scale),
                                    to_tf32((acc[fm][fn][1] + bv1) * scale));
            float2 v1 = make_float2(to_tf32((acc[fm][fn][2] + bv0) * scale),
                                    to_tf32((acc[fm][fn][3] + bv1) * scale));
            *reinterpret_cast<float2*>(&dstbase[(size_t)(r0)     * DK]) = v0;
            *reinterpret_cast<float2*>(&dstbase[(size_t)(r0 + 8) * DK]) = v1;
        }
    }
}

// ---------------------------------------------------------------------------
// Kernel 2: flash-style attention, Q-tile 128, 8 row-warps (16 q-rows each,
// ALL 64 keys per tile). P stays in registers: accumulator -> A-fragment
// layout conversion via in-quad shuffles. One __syncthreads per K/V tile.
// ---------------------------------------------------------------------------
#define QT   128
#define KSTR 68
#define VSTR 72
#define NKT  (SEQ / 64)

#define ATTN_SMEM_FLOATS (2*64*KSTR + 2*64*VSTR)
#define ATTN_SMEM_BYTES  (ATTN_SMEM_FLOATS * sizeof(float))

__global__ __launch_bounds__(256, 2)
void attn_kernel(float* __restrict__ out)
{
    extern __shared__ float sm[];
    float* Ks = sm;                       // 2 bufs of 64 x KSTR
    float* Vs = Ks + 2 * 64 * KSTR;       // 2 bufs of 64 x VSTR (also Q staging)

    const int bh = blockIdx.y;
    const int b  = bh >> 4;
    const int h  = bh & 15;
    const int q0 = blockIdx.x * QT;

    const float* Qp = g_Q + (size_t)bh * SEQ * DK + (size_t)q0 * DK;
    const float* Kp = g_K + (size_t)bh * SEQ * DK;
    const float* Vp = g_V + (size_t)bh * SEQ * DK;

    const int tid  = threadIdx.x;
    const int lane = tid & 31;
    const int warp = tid >> 5;            // 0..7 -> q rows warp*16
    const int g = lane >> 2;
    const int t = lane & 3;
    const int row0 = warp * 16;

    // Stage Q (128 x 64) into Vs area with stride 68, read fragments, then free
    #pragma unroll
    for (int it = 0; it < 8; it++) {
        int idx = tid + it * 256;          // 2048 float4
        int r = idx >> 4, c4 = (idx & 15) * 4;
        *reinterpret_cast<float4*>(&Vs[r * 68 + c4]) =
            *reinterpret_cast<const float4*>(&Qp[(size_t)r * DK + c4]);
    }
    __syncthreads();

    uint32_t qf[8][4];
    #pragma unroll
    for (int ks = 0; ks < 8; ks++) {
        qf[ks][0] = __float_as_uint(Vs[(row0 + g)     * 68 + 8 * ks + t]);
        qf[ks][1] = __float_as_uint(Vs[(row0 + g + 8) * 68 + 8 * ks + t]);
        qf[ks][2] = __float_as_uint(Vs[(row0 + g)     * 68 + 8 * ks + t + 4]);
        qf[ks][3] = __float_as_uint(Vs[(row0 + g + 8) * 68 + 8 * ks + t + 4]);
    }
    __syncthreads();   // all Q reads done before cp.async overwrites Vs

    // Prefetch K/V tile 0
    {
        #pragma unroll
        for (int it = 0; it < 4; it++) {
            int idx = tid + it * 256;
            int r = idx >> 4, c4 = (idx & 15) * 4;
            cp16(&Ks[r * KSTR + c4], Kp + (size_t)r * DK + c4);
            cp16(&Vs[r * VSTR + c4], Vp + (size_t)r * DK + c4);
        }
        cp_commit();
    }

    float oacc[8][4];
    #pragma unroll
    for (int jn = 0; jn < 8; jn++)
        #pragma unroll
        for (int e = 0; e < 4; e++) oacc[jn][e] = 0.0f;
    float rs0 = 0.0f, rs1 = 0.0f;

    const int srcA = (lane & 28) | (t >> 1);   // 4g + t/2
    const int srcB = srcA + 2;
    const bool odd = (t & 1);

    for (int kt = 0; kt < NKT; kt++) {
        const int buf = kt & 1;
        cp_wait_all();
        __syncthreads();

        if (kt + 1 < NKT) {
            const float* kp = Kp + (size_t)(kt + 1) * 64 * DK;
            const float* vp = Vp + (size_t)(kt + 1) * 64 * DK;
            float* Kn = Ks + (buf ^ 1) * 64 * KSTR;
            float* Vn = Vs + (buf ^ 1) * 64 * VSTR;
            #pragma unroll
            for (int it = 0; it < 4; it++) {
                int idx = tid + it * 256;
                int r = idx >> 4, c4 = (idx & 15) * 4;
                cp16(&Kn[r * KSTR + c4], kp + (size_t)r * DK + c4);
                cp16(&Vn[r * VSTR + c4], vp + (size_t)r * DK + c4);
            }
            cp_commit();
        }

        const float* Kb = Ks + buf * 64 * KSTR;
        const float* Vb = Vs + buf * 64 * VSTR;

        // S = Q @ K^T : 16 rows x 64 keys per warp (8 key-blocks)
        float sacc[8][4];
        #pragma unroll
        for (int j = 0; j < 8; j++)
            #pragma unroll
            for (int e = 0; e < 4; e++) sacc[j][e] = 0.0f;

        #pragma unroll
        for (int ks = 0; ks < 8; ks++) {
            #pragma unroll
            for (int j = 0; j < 8; j++) {
                int key = j * 8 + g;
                uint32_t b0 = __float_as_uint(Kb[key * KSTR + 8 * ks + t]);
                uint32_t b1 = __float_as_uint(Kb[key * KSTR + 8 * ks + t + 4]);
                mma_tf32(sacc[j], qf[ks], b0, b1);
            }
        }

        // exp in registers + rowsums (rowsum complete within warp)
        #pragma unroll
        for (int j = 0; j < 8; j++) {
            float e0 = __expf(sacc[j][0]);
            float e1 = __expf(sacc[j][1]);
            float e2 = __expf(sacc[j][2]);
            float e3 = __expf(sacc[j][3]);
            rs0 += e0 + e1;
            rs1 += e2 + e3;
            sacc[j][0] = to_tf32(e0); sacc[j][1] = to_tf32(e1);
            sacc[j][2] = to_tf32(e2); sacc[j][3] = to_tf32(e3);
        }

        // O += P @ V : P converted accumulator->A layout via quad shuffles.
        // kstep j covers keys j*8..j*8+7; A-frag needs cols {t, t+4}, we hold {2t,2t+1}.
        #pragma unroll
        for (int j = 0; j < 8; j++) {
            uint32_t a[4];
            {
                float x0A = __shfl_sync(0xffffffffu, sacc[j][0], srcA);
                float x1A = __shfl_sync(0xffffffffu, sacc[j][1], srcA);
                float x0B = __shfl_sync(0xffffffffu, sacc[j][0], srcB);
                float x1B = __shfl_sync(0xffffffffu, sacc[j][1], srcB);
                a[0] = __float_as_uint(odd ? x1A : x0A);
                a[2] = __float_as_uint(odd ? x1B : x0B);
                float y0A = __shfl_sync(0xffffffffu, sacc[j][2], srcA);
                float y1A = __shfl_sync(0xffffffffu, sacc[j][3], srcA);
                float y0B = __shfl_sync(0xffffffffu, sacc[j][2], srcB);
                float y1B = __shfl_sync(0xffffffffu, sacc[j][3], srcB);
                a[1] = __float_as_uint(odd ? y1A : y0A);
                a[3] = __float_as_uint(odd ? y1B : y0B);
            }
            #pragma unroll
            for (int jn = 0; jn < 8; jn++) {
                int dcol = jn * 8 + g;
                uint32_t b0 = __float_as_uint(Vb[(j * 8 + t)     * VSTR + dcol]);
                uint32_t b1 = __float_as_uint(Vb[(j * 8 + t + 4) * VSTR + dcol]);
                mma_tf32(oacc[jn], a, b0, b1);
            }
        }
    }

    // Row sums: reduce over the quad (t lanes)
    rs0 += __shfl_xor_sync(0xffffffffu, rs0, 1);
    rs0 += __shfl_xor_sync(0xffffffffu, rs0, 2);
    rs1 += __shfl_xor_sync(0xffffffffu, rs1, 1);
    rs1 += __shfl_xor_sync(0xffffffffu, rs1, 2);
    float inv0 = 1.0f / (rs0 + 1e-8f);
    float inv1 = 1.0f / (rs1 + 1e-8f);

    // Write O: out[b, q0+row, h*64 + col]
    #pragma unroll
    for (int jn = 0; jn < 8; jn++) {
        int dcol = jn * 8 + 2 * t;
        float* dst0 = out + ((size_t)(b * SEQ + q0 + row0 + g)) * DMODEL + h * DK + dcol;
        float* dst1 = dst0 + (size_t)8 * DMODEL;
        *reinterpret_cast<float2*>(dst0) = make_float2(oacc[jn][0] * inv0, oacc[jn][1] * inv0);
        *reinterpret_cast<float2*>(dst1) = make_float2(oacc[jn][2] * inv1, oacc[jn][3] * inv1);
    }
}

// ---------------------------------------------------------------------------
extern "C" void kernel_launch(void* const* d_in, const int* in_sizes, int n_in,
                              void* d_out, int out_size)
{
    const float* x  = (const float*)d_in[0];
    const float* Wq = (const float*)d_in[1];
    const float* bq = (const float*)d_in[2];
    const float* Wk = (const float*)d_in[3];
    const float* bk = (const float*)d_in[4];
    const float* Wv = (const float*)d_in[5];
    const float* bv = (const float*)d_in[6];
    float* out = (float*)d_out;

    cudaFuncSetAttribute(attn_kernel, cudaFuncAttributeMaxDynamicSharedMemorySize,
                         (int)ATTN_SMEM_BYTES);
    cudaFuncSetAttribute(qkv_gemm_kernel, cudaFuncAttributeMaxDynamicSharedMemorySize,
                         (int)GEMM_SMEM_BYTES);

    float* gx; cudaGetSymbolAddress((void**)&gx, g_X);
    float* gw; cudaGetSymbolAddress((void**)&gw, g_W);
    const int xn4 = MTOT * DMODEL / 4;
    const int wn4 = DMODEL * DMODEL / 4;
    round_copy<<<(xn4 + 255) / 256, 256>>>(x,  gx, xn4);
    round_copy<<<(wn4 + 255) / 256, 256>>>(Wq, gw, wn4);
    round_copy<<<(wn4 + 255) / 256, 256>>>(Wk, gw + (size_t)DMODEL * DMODEL, wn4);
    round_copy<<<(wn4 + 255) / 256, 256>>>(Wv, gw + (size_t)2 * DMODEL * DMODEL, wn4);

    dim3 gemm_grid(DMODEL / BN, MTOT / BM, 3);   // 8 x 32 x 3
    qkv_gemm_kernel<<<gemm_grid, 256, GEMM_SMEM_BYTES>>>(bq, bk, bv);

    dim3 attn_grid(SEQ / QT, BH);                // 16 x 32
    attn_kernel<<<attn_grid, 256, ATTN_SMEM_BYTES>>>(out);
}

// round 5
// speedup vs baseline: 2.7173x; 1.0359x over previous
#include <cuda_runtime.h>
#include <cuda_bf16.h>
#include <cstdint>

// Problem constants
#define BATCH   2
#define SEQ     2048
#define DMODEL  1024
#define NHEADS  16
#define DK      64
#define BH      (BATCH * NHEADS)          // 32
#define MTOT    (BATCH * SEQ)             // 4096

// Scratch: tf32-pre-rounded copies of X and W, and projected Q/K/V
__device__ float g_X[(size_t)MTOT * DMODEL];
__device__ float g_W[(size_t)3 * DMODEL * DMODEL];
__device__ float g_Q[(size_t)BH * SEQ * DK];
__device__ float g_K[(size_t)BH * SEQ * DK];
__device__ float g_V[(size_t)BH * SEQ * DK];

// ---------------------------------------------------------------------------
// Helpers
// ---------------------------------------------------------------------------
__device__ __forceinline__ float to_tf32(float x) {
    uint32_t u;
    asm("cvt.rna.tf32.f32 %0, %1;" : "=r"(u) : "f"(x));
    return __uint_as_float(u);
}

__device__ __forceinline__ void mma_tf32(float c[4], const uint32_t a[4],
                                         uint32_t b0, uint32_t b1) {
    asm volatile(
        "mma.sync.aligned.m16n8k8.row.col.f32.tf32.tf32.f32 "
        "{%0,%1,%2,%3}, {%4,%5,%6,%7}, {%8,%9}, {%0,%1,%2,%3};"
        : "+f"(c[0]), "+f"(c[1]), "+f"(c[2]), "+f"(c[3])
        : "r"(a[0]), "r"(a[1]), "r"(a[2]), "r"(a[3]), "r"(b0), "r"(b1));
}

__device__ __forceinline__ void cp16(void* s, const void* gp) {
    uint32_t sa = (uint32_t)__cvta_generic_to_shared(s);
    asm volatile("cp.async.cg.shared.global [%0], [%1], 16;" :: "r"(sa), "l"(gp));
}
__device__ __forceinline__ void cp_commit() {
    asm volatile("cp.async.commit_group;");
}
__device__ __forceinline__ void cp_wait_all() {
    asm volatile("cp.async.wait_group 0;");
}

// ---------------------------------------------------------------------------
// Kernel 0: elementwise tf32 pre-round (float4 vectorized)
// ---------------------------------------------------------------------------
__global__ void round_copy(const float* __restrict__ src, float* __restrict__ dst, int n4)
{
    int i = blockIdx.x * blockDim.x + threadIdx.x;
    if (i < n4) {
        float4 v = reinterpret_cast<const float4*>(src)[i];
        v.x = to_tf32(v.x); v.y = to_tf32(v.y);
        v.z = to_tf32(v.z); v.w = to_tf32(v.w);
        reinterpret_cast<float4*>(dst)[i] = v;
    }
}

// One launch for the 3 weight matrices (blockIdx.y selects)
__global__ void round_copy_w(const float* __restrict__ w0,
                             const float* __restrict__ w1,
                             const float* __restrict__ w2,
                             float* __restrict__ dst, int n4)
{
    const float* src = (blockIdx.y == 0) ? w0 : (blockIdx.y == 1) ? w1 : w2;
    float* d = dst + (size_t)blockIdx.y * DMODEL * DMODEL;
    int i = blockIdx.x * blockDim.x + threadIdx.x;
    if (i < n4) {
        float4 v = reinterpret_cast<const float4*>(src)[i];
        v.x = to_tf32(v.x); v.y = to_tf32(v.y);
        v.z = to_tf32(v.z); v.w = to_tf32(v.w);
        reinterpret_cast<float4*>(d)[i] = v;
    }
}

// ---------------------------------------------------------------------------
// Kernel 1: QKV projection GEMM. out[m,n] = sum_k X[m,k]*W[k,n] + b[n]
// BM=256, BN=128, BK=32. 8 warps as 4x2; warp tile 64x64 (fm=4, fn=8).
// LDS.32 per MMA = 1.0. cp.async double buffer. Register epilogue scatters
// into [bh,s,d] scratch with bias (+0.125 for Q) + tf32 round.
// ---------------------------------------------------------------------------
#define BM 256
#define BN 128
#define BK 32
#define ASTR 36
#define BSTR 136
#define GEMM_SMEM_FLOATS (2 * BM * ASTR + 2 * BK * BSTR)
#define GEMM_SMEM_BYTES  (GEMM_SMEM_FLOATS * sizeof(float))
#define NKTILES (DMODEL / BK)

__global__ __launch_bounds__(256, 1)
void qkv_gemm_kernel(const float* __restrict__ bq,
                     const float* __restrict__ bk,
                     const float* __restrict__ bv)
{
    extern __shared__ float sg[];
    float* As = sg;                        // 2 bufs of BM x ASTR
    float* Bs = sg + 2 * BM * ASTR;        // 2 bufs of BK x BSTR

    const float* W;
    const float* bias;
    float* Out;
    if (blockIdx.z == 0)      { W = g_W;                               bias = bq; Out = g_Q; }
    else if (blockIdx.z == 1) { W = g_W + (size_t)DMODEL * DMODEL;     bias = bk; Out = g_K; }
    else                      { W = g_W + (size_t)2 * DMODEL * DMODEL; bias = bv; Out = g_V; }

    const int m0 = blockIdx.y * BM;
    const int n0 = blockIdx.x * BN;
    const int tid  = threadIdx.x;
    const int lane = tid & 31;
    const int warp = tid >> 5;
    const int g = lane >> 2;
    const int t = lane & 3;
    const int wm = warp >> 1;     // 0..3 -> rows 64*wm
    const int wn = warp & 1;      // 0..1 -> cols 64*wn

    const float* Xp = g_X + (size_t)m0 * DMODEL;

    // Prefetch tile 0
    {
        #pragma unroll
        for (int it = 0; it < 8; it++) {     // A: 256 x 32 = 2048 float4
            int idx = tid + it * 256;
            int r = idx >> 3, c4 = (idx & 7) * 4;
            cp16(&As[r * ASTR + c4], Xp + (size_t)r * DMODEL + c4);
        }
        #pragma unroll
        for (int it = 0; it < 4; it++) {     // B: 32 x 128 = 1024 float4
            int idx = tid + it * 256;
            int r = idx >> 5, c4 = (idx & 31) * 4;
            cp16(&Bs[r * BSTR + c4], W + (size_t)r * DMODEL + n0 + c4);
        }
        cp_commit();
    }

    float acc[4][8][4];
    #pragma unroll
    for (int fm = 0; fm < 4; fm++)
        #pragma unroll
        for (int fn = 0; fn < 8; fn++)
            #pragma unroll
            for (int e = 0; e < 4; e++) acc[fm][fn][e] = 0.0f;

    for (int kt = 0; kt < NKTILES; kt++) {
        const int buf = kt & 1;
        cp_wait_all();
        __syncthreads();

        if (kt + 1 < NKTILES) {
            const int k0n = (kt + 1) * BK;
            float* An = As + (buf ^ 1) * BM * ASTR;
            float* Bn = Bs + (buf ^ 1) * BK * BSTR;
            #pragma unroll
            for (int it = 0; it < 8; it++) {
                int idx = tid + it * 256;
                int r = idx >> 3, c4 = (idx & 7) * 4;
                cp16(&An[r * ASTR + c4], Xp + (size_t)r * DMODEL + k0n + c4);
            }
            #pragma unroll
            for (int it = 0; it < 4; it++) {
                int idx = tid + it * 256;
                int r = idx >> 5, c4 = (idx & 31) * 4;
                cp16(&Bn[r * BSTR + c4], W + (size_t)(k0n + r) * DMODEL + n0 + c4);
            }
            cp_commit();
        }

        const float* Ab = As + buf * BM * ASTR;
        const float* Bb = Bs + buf * BK * BSTR;

        #pragma unroll
        for (int ks = 0; ks < 4; ks++) {
            uint32_t a[4][4];
            #pragma unroll
            for (int fm = 0; fm < 4; fm++) {
                int rb = wm * 64 + fm * 16;
                a[fm][0] = __float_as_uint(Ab[(rb + g)     * ASTR + 8 * ks + t]);
                a[fm][1] = __float_as_uint(Ab[(rb + g + 8) * ASTR + 8 * ks + t]);
                a[fm][2] = __float_as_uint(Ab[(rb + g)     * ASTR + 8 * ks + t + 4]);
                a[fm][3] = __float_as_uint(Ab[(rb + g + 8) * ASTR + 8 * ks + t + 4]);
            }
            #pragma unroll
            for (int fn = 0; fn < 8; fn++) {
                int col = wn * 64 + fn * 8 + g;
                uint32_t b0 = __float_as_uint(Bb[(8 * ks + t)     * BSTR + col]);
                uint32_t b1 = __float_as_uint(Bb[(8 * ks + t + 4) * BSTR + col]);
                #pragma unroll
                for (int fm = 0; fm < 4; fm++) mma_tf32(acc[fm][fn], a[fm], b0, b1);
            }
        }
    }

    // Register epilogue: bias (+ Q scale) + tf32 round, scatter to [bh,s,d]
    const int b  = m0 / SEQ;              // BM divides SEQ
    const int s0 = m0 % SEQ;
    const int h0 = n0 >> 6;               // BN=128 spans 2 heads
    const float scale = (blockIdx.z == 0) ? 0.125f : 1.0f;

    #pragma unroll
    for (int fm = 0; fm < 4; fm++) {
        int r0 = wm * 64 + fm * 16 + g;
        #pragma unroll
        for (int fn = 0; fn < 8; fn++) {
            int c = wn * 64 + fn * 8 + 2 * t;
            int h = h0 + (c >> 6);
            int cc = c & 63;
            float bv0 = bias[n0 + c];
            float bv1 = bias[n0 + c + 1];
            float* dstbase = Out + ((size_t)(b * NHEADS + h) * SEQ + s0) * DK + cc;
            float2 v0 = make_float2(to_tf32((acc[fm][fn][0] + bv0) * scale),
                                    to_tf32((acc[fm][fn][1] + bv1) * scale));
            float2 v1 = make_float2(to_tf32((acc[fm][fn][2] + bv0) * scale),
                                    to_tf32((acc[fm][fn][3] + bv1) * scale));
            *reinterpret_cast<float2*>(&dstbase[(size_t)(r0)     * DK]) = v0;
            *reinterpret_cast<float2*>(&dstbase[(size_t)(r0 + 8) * DK]) = v1;
        }
    }
}

// ---------------------------------------------------------------------------
// Kernel 2: flash-style attention, Q-tile 128, 8 row-warps (16 q-rows each,
// ALL 64 keys per tile). P stays in registers via in-quad shuffle transpose.
// One __syncthreads per K/V tile. (unchanged from R4 except cp.async.cg)
// ---------------------------------------------------------------------------
#define QT   128
#define KSTR 68
#define VSTR 72
#define NKT  (SEQ / 64)

#define ATTN_SMEM_FLOATS (2*64*KSTR + 2*64*VSTR)
#define ATTN_SMEM_BYTES  (ATTN_SMEM_FLOATS * sizeof(float))

__global__ __launch_bounds__(256, 2)
void attn_kernel(float* __restrict__ out)
{
    extern __shared__ float sm[];
    float* Ks = sm;                       // 2 bufs of 64 x KSTR
    float* Vs = Ks + 2 * 64 * KSTR;       // 2 bufs of 64 x VSTR (also Q staging)

    const int bh = blockIdx.y;
    const int b  = bh >> 4;
    const int h  = bh & 15;
    const int q0 = blockIdx.x * QT;

    const float* Qp = g_Q + (size_t)bh * SEQ * DK + (size_t)q0 * DK;
    const float* Kp = g_K + (size_t)bh * SEQ * DK;
    const float* Vp = g_V + (size_t)bh * SEQ * DK;

    const int tid  = threadIdx.x;
    const int lane = tid & 31;
    const int warp = tid >> 5;            // 0..7 -> q rows warp*16
    const int g = lane >> 2;
    const int t = lane & 3;
    const int row0 = warp * 16;

    // Stage Q (128 x 64) into Vs area with stride 68, read fragments, then free
    #pragma unroll
    for (int it = 0; it < 8; it++) {
        int idx = tid + it * 256;          // 2048 float4
        int r = idx >> 4, c4 = (idx & 15) * 4;
        *reinterpret_cast<float4*>(&Vs[r * 68 + c4]) =
            *reinterpret_cast<const float4*>(&Qp[(size_t)r * DK + c4]);
    }
    __syncthreads();

    uint32_t qf[8][4];
    #pragma unroll
    for (int ks = 0; ks < 8; ks++) {
        qf[ks][0] = __float_as_uint(Vs[(row0 + g)     * 68 + 8 * ks + t]);
        qf[ks][1] = __float_as_uint(Vs[(row0 + g + 8) * 68 + 8 * ks + t]);
        qf[ks][2] = __float_as_uint(Vs[(row0 + g)     * 68 + 8 * ks + t + 4]);
        qf[ks][3] = __float_as_uint(Vs[(row0 + g + 8) * 68 + 8 * ks + t + 4]);
    }
    __syncthreads();   // all Q reads done before cp.async overwrites Vs

    // Prefetch K/V tile 0
    {
        #pragma unroll
        for (int it = 0; it < 4; it++) {
            int idx = tid + it * 256;
            int r = idx >> 4, c4 = (idx & 15) * 4;
            cp16(&Ks[r * KSTR + c4], Kp + (size_t)r * DK + c4);
            cp16(&Vs[r * VSTR + c4], Vp + (size_t)r * DK + c4);
        }
        cp_commit();
    }

    float oacc[8][4];
    #pragma unroll
    for (int jn = 0; jn < 8; jn++)
        #pragma unroll
        for (int e = 0; e < 4; e++) oacc[jn][e] = 0.0f;
    float rs0 = 0.0f, rs1 = 0.0f;

    const int srcA = (lane & 28) | (t >> 1);   // 4g + t/2
    const int srcB = srcA + 2;
    const bool odd = (t & 1);

    for (int kt = 0; kt < NKT; kt++) {
        const int buf = kt & 1;
        cp_wait_all();
        __syncthreads();

        if (kt + 1 < NKT) {
            const float* kp = Kp + (size_t)(kt + 1) * 64 * DK;
            const float* vp = Vp + (size_t)(kt + 1) * 64 * DK;
            float* Kn = Ks + (buf ^ 1) * 64 * KSTR;
            float* Vn = Vs + (buf ^ 1) * 64 * VSTR;
            #pragma unroll
            for (int it = 0; it < 4; it++) {
                int idx = tid + it * 256;
                int r = idx >> 4, c4 = (idx & 15) * 4;
                cp16(&Kn[r * KSTR + c4], kp + (size_t)r * DK + c4);
                cp16(&Vn[r * VSTR + c4], vp + (size_t)r * DK + c4);
            }
            cp_commit();
        }

        const float* Kb = Ks + buf * 64 * KSTR;
        const float* Vb = Vs + buf * 64 * VSTR;

        // S = Q @ K^T : 16 rows x 64 keys per warp (8 key-blocks)
        float sacc[8][4];
        #pragma unroll
        for (int j = 0; j < 8; j++)
            #pragma unroll
            for (int e = 0; e < 4; e++) sacc[j][e] = 0.0f;

        #pragma unroll
        for (int ks = 0; ks < 8; ks++) {
            #pragma unroll
            for (int j = 0; j < 8; j++) {
                int key = j * 8 + g;
                uint32_t b0 = __float_as_uint(Kb[key * KSTR + 8 * ks + t]);
                uint32_t b1 = __float_as_uint(Kb[key * KSTR + 8 * ks + t + 4]);
                mma_tf32(sacc[j], qf[ks], b0, b1);
            }
        }

        // exp in registers + rowsums (rowsum complete within warp)
        #pragma unroll
        for (int j = 0; j < 8; j++) {
            float e0 = __expf(sacc[j][0]);
            float e1 = __expf(sacc[j][1]);
            float e2 = __expf(sacc[j][2]);
            float e3 = __expf(sacc[j][3]);
            rs0 += e0 + e1;
            rs1 += e2 + e3;
            sacc[j][0] = to_tf32(e0); sacc[j][1] = to_tf32(e1);
            sacc[j][2] = to_tf32(e2); sacc[j][3] = to_tf32(e3);
        }

        // O += P @ V : P converted accumulator->A layout via quad shuffles.
        #pragma unroll
        for (int j = 0; j < 8; j++) {
            uint32_t a[4];
            {
                float x0A = __shfl_sync(0xffffffffu, sacc[j][0], srcA);
                float x1A = __shfl_sync(0xffffffffu, sacc[j][1], srcA);
                float x0B = __shfl_sync(0xffffffffu, sacc[j][0], srcB);
                float x1B = __shfl_sync(0xffffffffu, sacc[j][1], srcB);
                a[0] = __float_as_uint(odd ? x1A : x0A);
                a[2] = __float_as_uint(odd ? x1B : x0B);
                float y0A = __shfl_sync(0xffffffffu, sacc[j][2], srcA);
                float y1A = __shfl_sync(0xffffffffu, sacc[j][3], srcA);
                float y0B = __shfl_sync(0xffffffffu, sacc[j][2], srcB);
                float y1B = __shfl_sync(0xffffffffu, sacc[j][3], srcB);
                a[1] = __float_as_uint(odd ? y1A : y0A);
                a[3] = __float_as_uint(odd ? y1B : y0B);
            }
            #pragma unroll
            for (int jn = 0; jn < 8; jn++) {
                int dcol = jn * 8 + g;
                uint32_t b0 = __float_as_uint(Vb[(j * 8 + t)     * VSTR + dcol]);
                uint32_t b1 = __float_as_uint(Vb[(j * 8 + t + 4) * VSTR + dcol]);
                mma_tf32(oacc[jn], a, b0, b1);
            }
        }
    }

    // Row sums: reduce over the quad (t lanes)
    rs0 += __shfl_xor_sync(0xffffffffu, rs0, 1);
    rs0 += __shfl_xor_sync(0xffffffffu, rs0, 2);
    rs1 += __shfl_xor_sync(0xffffffffu, rs1, 1);
    rs1 += __shfl_xor_sync(0xffffffffu, rs1, 2);
    float inv0 = 1.0f / (rs0 + 1e-8f);
    float inv1 = 1.0f / (rs1 + 1e-8f);

    // Write O: out[b, q0+row, h*64 + col]
    #pragma unroll
    for (int jn = 0; jn < 8; jn++) {
        int dcol = jn * 8 + 2 * t;
        float* dst0 = out + ((size_t)(b * SEQ + q0 + row0 + g)) * DMODEL + h * DK + dcol;
        float* dst1 = dst0 + (size_t)8 * DMODEL;
        *reinterpret_cast<float2*>(dst0) = make_float2(oacc[jn][0] * inv0, oacc[jn][1] * inv0);
        *reinterpret_cast<float2*>(dst1) = make_float2(oacc[jn][2] * inv1, oacc[jn][3] * inv1);
    }
}

// ---------------------------------------------------------------------------
extern "C" void kernel_launch(void* const* d_in, const int* in_sizes, int n_in,
                              void* d_out, int out_size)
{
    const float* x  = (const float*)d_in[0];
    const float* Wq = (const float*)d_in[1];
    const float* bq = (const float*)d_in[2];
    const float* Wk = (const float*)d_in[3];
    const float* bk = (const float*)d_in[4];
    const float* Wv = (const float*)d_in[5];
    const float* bv = (const float*)d_in[6];
    float* out = (float*)d_out;

    cudaFuncSetAttribute(attn_kernel, cudaFuncAttributeMaxDynamicSharedMemorySize,
                         (int)ATTN_SMEM_BYTES);
    cudaFuncSetAttribute(qkv_gemm_kernel, cudaFuncAttributeMaxDynamicSharedMemorySize,
                         (int)GEMM_SMEM_BYTES);

    float* gx; cudaGetSymbolAddress((void**)&gx, g_X);
    float* gw; cudaGetSymbolAddress((void**)&gw, g_W);
    const int xn4 = MTOT * DMODEL / 4;
    const int wn4 = DMODEL * DMODEL / 4;
    round_copy<<<(xn4 + 255) / 256, 256>>>(x, gx, xn4);
    dim3 wgrid((wn4 + 255) / 256, 3);
    round_copy_w<<<wgrid, 256>>>(Wq, Wk, Wv, gw, wn4);

    dim3 gemm_grid(DMODEL / BN, MTOT / BM, 3);   // 8 x 16 x 3
    qkv_gemm_kernel<<<gemm_grid, 256, GEMM_SMEM_BYTES>>>(bq, bk, bv);

    dim3 attn_grid(SEQ / QT, BH);                // 16 x 32
    attn_kernel<<<attn_grid, 256, ATTN_SMEM_BYTES>>>(out);
}

// round 10
// speedup vs baseline: 3.0367x; 1.1176x over previous
#include <cuda_runtime.h>
#include <cuda_bf16.h>
#include <cstdint>

// Problem constants
#define BATCH   2
#define SEQ     2048
#define DMODEL  1024
#define NHEADS  16
#define DK      64
#define BH      (BATCH * NHEADS)          // 32
#define MTOT    (BATCH * SEQ)             // 4096

// Scratch: tf32-pre-rounded copies of X and W, and projected Q/K/V
__device__ float g_X[(size_t)MTOT * DMODEL];
__device__ float g_W[(size_t)3 * DMODEL * DMODEL];
__device__ float g_Q[(size_t)BH * SEQ * DK];
__device__ float g_K[(size_t)BH * SEQ * DK];
__device__ float g_V[(size_t)BH * SEQ * DK];

// ---------------------------------------------------------------------------
// Helpers
// ---------------------------------------------------------------------------
__device__ __forceinline__ float to_tf32(float x) {
    uint32_t u;
    asm("cvt.rna.tf32.f32 %0, %1;" : "=r"(u) : "f"(x));
    return __uint_as_float(u);
}

__device__ __forceinline__ void mma_tf32(float c[4], const uint32_t a[4],
                                         uint32_t b0, uint32_t b1) {
    asm volatile(
        "mma.sync.aligned.m16n8k8.row.col.f32.tf32.tf32.f32 "
        "{%0,%1,%2,%3}, {%4,%5,%6,%7}, {%8,%9}, {%0,%1,%2,%3};"
        : "+f"(c[0]), "+f"(c[1]), "+f"(c[2]), "+f"(c[3])
        : "r"(a[0]), "r"(a[1]), "r"(a[2]), "r"(a[3]), "r"(b0), "r"(b1));
}

__device__ __forceinline__ void cp16(void* s, const void* gp) {
    uint32_t sa = (uint32_t)__cvta_generic_to_shared(s);
    asm volatile("cp.async.cg.shared.global [%0], [%1], 16;" :: "r"(sa), "l"(gp));
}
__device__ __forceinline__ void cp_commit() {
    asm volatile("cp.async.commit_group;");
}
__device__ __forceinline__ void cp_wait_all() {
    asm volatile("cp.async.wait_group 0;");
}

// ---------------------------------------------------------------------------
// Kernel 0: elementwise tf32 pre-round (float4 vectorized)
// ---------------------------------------------------------------------------
__global__ void round_copy(const float* __restrict__ src, float* __restrict__ dst, int n4)
{
    int i = blockIdx.x * blockDim.x + threadIdx.x;
    if (i < n4) {
        float4 v = reinterpret_cast<const float4*>(src)[i];
        v.x = to_tf32(v.x); v.y = to_tf32(v.y);
        v.z = to_tf32(v.z); v.w = to_tf32(v.w);
        reinterpret_cast<float4*>(dst)[i] = v;
    }
}

// One launch for the 3 weight matrices (blockIdx.y selects)
__global__ void round_copy_w(const float* __restrict__ w0,
                             const float* __restrict__ w1,
                             const float* __restrict__ w2,
                             float* __restrict__ dst, int n4)
{
    const float* src = (blockIdx.y == 0) ? w0 : (blockIdx.y == 1) ? w1 : w2;
    float* d = dst + (size_t)blockIdx.y * DMODEL * DMODEL;
    int i = blockIdx.x * blockDim.x + threadIdx.x;
    if (i < n4) {
        float4 v = reinterpret_cast<const float4*>(src)[i];
        v.x = to_tf32(v.x); v.y = to_tf32(v.y);
        v.z = to_tf32(v.z); v.w = to_tf32(v.w);
        reinterpret_cast<float4*>(d)[i] = v;
    }
}

// ---------------------------------------------------------------------------
// Kernel 1: QKV projection GEMM (R5 version). out[m,n] = X@W + b.
// BM=256, BN=128, BK=32. 8 warps as 4x2; warp tile 64x64.
// ---------------------------------------------------------------------------
#define BM 256
#define BN 128
#define BK 32
#define ASTR 36
#define BSTR 136
#define GEMM_SMEM_FLOATS (2 * BM * ASTR + 2 * BK * BSTR)
#define GEMM_SMEM_BYTES  (GEMM_SMEM_FLOATS * sizeof(float))
#define NKTILES (DMODEL / BK)

__global__ __launch_bounds__(256, 1)
void qkv_gemm_kernel(const float* __restrict__ bq,
                     const float* __restrict__ bk,
                     const float* __restrict__ bv)
{
    extern __shared__ float sg[];
    float* As = sg;
    float* Bs = sg + 2 * BM * ASTR;

    const float* W;
    const float* bias;
    float* Out;
    if (blockIdx.z == 0)      { W = g_W;                               bias = bq; Out = g_Q; }
    else if (blockIdx.z == 1) { W = g_W + (size_t)DMODEL * DMODEL;     bias = bk; Out = g_K; }
    else                      { W = g_W + (size_t)2 * DMODEL * DMODEL; bias = bv; Out = g_V; }

    const int m0 = blockIdx.y * BM;
    const int n0 = blockIdx.x * BN;
    const int tid  = threadIdx.x;
    const int lane = tid & 31;
    const int warp = tid >> 5;
    const int g = lane >> 2;
    const int t = lane & 3;
    const int wm = warp >> 1;
    const int wn = warp & 1;

    const float* Xp = g_X + (size_t)m0 * DMODEL;

    {
        #pragma unroll
        for (int it = 0; it < 8; it++) {
            int idx = tid + it * 256;
            int r = idx >> 3, c4 = (idx & 7) * 4;
            cp16(&As[r * ASTR + c4], Xp + (size_t)r * DMODEL + c4);
        }
        #pragma unroll
        for (int it = 0; it < 4; it++) {
            int idx = tid + it * 256;
            int r = idx >> 5, c4 = (idx & 31) * 4;
            cp16(&Bs[r * BSTR + c4], W + (size_t)r * DMODEL + n0 + c4);
        }
        cp_commit();
    }

    float acc[4][8][4];
    #pragma unroll
    for (int fm = 0; fm < 4; fm++)
        #pragma unroll
        for (int fn = 0; fn < 8; fn++)
            #pragma unroll
            for (int e = 0; e < 4; e++) acc[fm][fn][e] = 0.0f;

    for (int kt = 0; kt < NKTILES; kt++) {
        const int buf = kt & 1;
        cp_wait_all();
        __syncthreads();

        if (kt + 1 < NKTILES) {
            const int k0n = (kt + 1) * BK;
            float* An = As + (buf ^ 1) * BM * ASTR;
            float* Bn = Bs + (buf ^ 1) * BK * BSTR;
            #pragma unroll
            for (int it = 0; it < 8; it++) {
                int idx = tid + it * 256;
                int r = idx >> 3, c4 = (idx & 7) * 4;
                cp16(&An[r * ASTR + c4], Xp + (size_t)r * DMODEL + k0n + c4);
            }
            #pragma unroll
            for (int it = 0; it < 4; it++) {
                int idx = tid + it * 256;
                int r = idx >> 5, c4 = (idx & 31) * 4;
                cp16(&Bn[r * BSTR + c4], W + (size_t)(k0n + r) * DMODEL + n0 + c4);
            }
            cp_commit();
        }

        const float* Ab = As + buf * BM * ASTR;
        const float* Bb = Bs + buf * BK * BSTR;

        #pragma unroll
        for (int ks = 0; ks < 4; ks++) {
            uint32_t a[4][4];
            #pragma unroll
            for (int fm = 0; fm < 4; fm++) {
                int rb = wm * 64 + fm * 16;
                a[fm][0] = __float_as_uint(Ab[(rb + g)     * ASTR + 8 * ks + t]);
                a[fm][1] = __float_as_uint(Ab[(rb + g + 8) * ASTR + 8 * ks + t]);
                a[fm][2] = __float_as_uint(Ab[(rb + g)     * ASTR + 8 * ks + t + 4]);
                a[fm][3] = __float_as_uint(Ab[(rb + g + 8) * ASTR + 8 * ks + t + 4]);
            }
            #pragma unroll
            for (int fn = 0; fn < 8; fn++) {
                int col = wn * 64 + fn * 8 + g;
                uint32_t b0 = __float_as_uint(Bb[(8 * ks + t)     * BSTR + col]);
                uint32_t b1 = __float_as_uint(Bb[(8 * ks + t + 4) * BSTR + col]);
                #pragma unroll
                for (int fm = 0; fm < 4; fm++) mma_tf32(acc[fm][fn], a[fm], b0, b1);
            }
        }
    }

    const int b  = m0 / SEQ;
    const int s0 = m0 % SEQ;
    const int h0 = n0 >> 6;
    const float scale = (blockIdx.z == 0) ? 0.125f : 1.0f;

    #pragma unroll
    for (int fm = 0; fm < 4; fm++) {
        int r0 = wm * 64 + fm * 16 + g;
        #pragma unroll
        for (int fn = 0; fn < 8; fn++) {
            int c = wn * 64 + fn * 8 + 2 * t;
            int h = h0 + (c >> 6);
            int cc = c & 63;
            float bv0 = bias[n0 + c];
            float bv1 = bias[n0 + c + 1];
            float* dstbase = Out + ((size_t)(b * NHEADS + h) * SEQ + s0) * DK + cc;
            float2 v0 = make_float2(to_tf32((acc[fm][fn][0] + bv0) * scale),
                                    to_tf32((acc[fm][fn][1] + bv1) * scale));
            float2 v1 = make_float2(to_tf32((acc[fm][fn][2] + bv0) * scale),
                                    to_tf32((acc[fm][fn][3] + bv1) * scale));
            *reinterpret_cast<float2*>(&dstbase[(size_t)(r0)     * DK]) = v0;
            *reinterpret_cast<float2*>(&dstbase[(size_t)(r0 + 8) * DK]) = v1;
        }
    }
}

// ---------------------------------------------------------------------------
// Kernel 2: flash attention, Q-tile 256, 8 warps x 32 rows (fm=2).
// Fused per-8-key-group pipeline: S-mma -> exp -> shuffle-transpose -> PV-mma,
// so the S accumulator is an 8-register transient. LDS bytes per q-row are
// HALF of the R5 kernel. One __syncthreads per K/V tile.
// ---------------------------------------------------------------------------
#define QT   256
#define KSTR 68
#define VSTR 72
#define NKT  (SEQ / 64)

#define ATTN_SMEM_FLOATS (2*64*KSTR + 2*64*VSTR)
#define ATTN_SMEM_BYTES  (ATTN_SMEM_FLOATS * sizeof(float))

__global__ __launch_bounds__(256, 1)
void attn_kernel(float* __restrict__ out)
{
    extern __shared__ float sm[];
    float* Ks = sm;                       // 2 bufs of 64 x KSTR
    float* Vs = Ks + 2 * 64 * KSTR;       // 2 bufs of 64 x VSTR

    const int bh = blockIdx.y;
    const int b  = bh >> 4;
    const int h  = bh & 15;
    const int q0 = blockIdx.x * QT;

    const float* Qp = g_Q + (size_t)bh * SEQ * DK + (size_t)q0 * DK;
    const float* Kp = g_K + (size_t)bh * SEQ * DK;
    const float* Vp = g_V + (size_t)bh * SEQ * DK;

    const int tid  = threadIdx.x;
    const int lane = tid & 31;
    const int warp = tid >> 5;            // 0..7 -> q rows warp*32
    const int g = lane >> 2;
    const int t = lane & 3;
    const int row0 = warp * 32;

    // Q fragments: half A = rows row0..+15, half B = rows row0+16..+31
    uint32_t qfA[8][4], qfB[8][4];
    #pragma unroll
    for (int p = 0; p < 2; p++) {
        // stage 128 q-rows (p*128..) into smem, stride 68
        #pragma unroll
        for (int it = 0; it < 8; it++) {
            int idx = tid + it * 256;      // 2048 float4
            int r = idx >> 4, c4 = (idx & 15) * 4;
            *reinterpret_cast<float4*>(&sm[r * 68 + c4]) =
                *reinterpret_cast<const float4*>(&Qp[(size_t)(p * 128 + r) * DK + c4]);
        }
        __syncthreads();
        if ((row0 >> 7) == p) {            // this warp's rows live in this pass
            int lr = row0 & 127;
            #pragma unroll
            for (int ks = 0; ks < 8; ks++) {
                qfA[ks][0] = __float_as_uint(sm[(lr + g)      * 68 + 8 * ks + t]);
                qfA[ks][1] = __float_as_uint(sm[(lr + g + 8)  * 68 + 8 * ks + t]);
                qfA[ks][2] = __float_as_uint(sm[(lr + g)      * 68 + 8 * ks + t + 4]);
                qfA[ks][3] = __float_as_uint(sm[(lr + g + 8)  * 68 + 8 * ks + t + 4]);
                qfB[ks][0] = __float_as_uint(sm[(lr + g + 16) * 68 + 8 * ks + t]);
                qfB[ks][1] = __float_as_uint(sm[(lr + g + 24) * 68 + 8 * ks + t]);
                qfB[ks][2] = __float_as_uint(sm[(lr + g + 16) * 68 + 8 * ks + t + 4]);
                qfB[ks][3] = __float_as_uint(sm[(lr + g + 24) * 68 + 8 * ks + t + 4]);
            }
        }
        __syncthreads();
    }

    // Prefetch K/V tile 0
    {
        #pragma unroll
        for (int it = 0; it < 4; it++) {
            int idx = tid + it * 256;
            int r = idx >> 4, c4 = (idx & 15) * 4;
            cp16(&Ks[r * KSTR + c4], Kp + (size_t)r * DK + c4);
            cp16(&Vs[r * VSTR + c4], Vp + (size_t)r * DK + c4);
        }
        cp_commit();
    }

    float oaccA[8][4], oaccB[8][4];
    #pragma unroll
    for (int jn = 0; jn < 8; jn++)
        #pragma unroll
        for (int e = 0; e < 4; e++) { oaccA[jn][e] = 0.0f; oaccB[jn][e] = 0.0f; }
    float rsA0 = 0.0f, rsA1 = 0.0f, rsB0 = 0.0f, rsB1 = 0.0f;

    const int srcA = (lane & 28) | (t >> 1);   // 4g + t/2
    const int srcB = srcA + 2;
    const bool odd = (t & 1);

    for (int kt = 0; kt < NKT; kt++) {
        const int buf = kt & 1;
        cp_wait_all();
        __syncthreads();

        if (kt + 1 < NKT) {
            const float* kp = Kp + (size_t)(kt + 1) * 64 * DK;
            const float* vp = Vp + (size_t)(kt + 1) * 64 * DK;
            float* Kn = Ks + (buf ^ 1) * 64 * KSTR;
            float* Vn = Vs + (buf ^ 1) * 64 * VSTR;
            #pragma unroll
            for (int it = 0; it < 4; it++) {
                int idx = tid + it * 256;
                int r = idx >> 4, c4 = (idx & 15) * 4;
                cp16(&Kn[r * KSTR + c4], kp + (size_t)r * DK + c4);
                cp16(&Vn[r * VSTR + c4], vp + (size_t)r * DK + c4);
            }
            cp_commit();
        }

        const float* Kb = Ks + buf * 64 * KSTR;
        const float* Vb = Vs + buf * 64 * VSTR;

        // Fused per-key-group pipeline: S -> exp -> transpose -> PV
        #pragma unroll
        for (int j = 0; j < 8; j++) {
            float s0[4] = {0.f, 0.f, 0.f, 0.f};
            float s1[4] = {0.f, 0.f, 0.f, 0.f};
            #pragma unroll
            for (int ks = 0; ks < 8; ks++) {
                int key = j * 8 + g;
                uint32_t b0 = __float_as_uint(Kb[key * KSTR + 8 * ks + t]);
                uint32_t b1 = __float_as_uint(Kb[key * KSTR + 8 * ks + t + 4]);
                mma_tf32(s0, qfA[ks], b0, b1);
                mma_tf32(s1, qfB[ks], b0, b1);
            }

            // exp + rowsums + tf32 round (half A)
            {
                float e0 = __expf(s0[0]), e1 = __expf(s0[1]);
                float e2 = __expf(s0[2]), e3 = __expf(s0[3]);
                rsA0 += e0 + e1; rsA1 += e2 + e3;
                s0[0] = to_tf32(e0); s0[1] = to_tf32(e1);
                s0[2] = to_tf32(e2); s0[3] = to_tf32(e3);
            }
            // half B
            {
                float e0 = __expf(s1[0]), e1 = __expf(s1[1]);
                float e2 = __expf(s1[2]), e3 = __expf(s1[3]);
                rsB0 += e0 + e1; rsB1 += e2 + e3;
                s1[0] = to_tf32(e0); s1[1] = to_tf32(e1);
                s1[2] = to_tf32(e2); s1[3] = to_tf32(e3);
            }

            // transpose accumulator -> A-fragment layout (both halves)
            uint32_t aA[4], aB[4];
            {
                float x0A = __shfl_sync(0xffffffffu, s0[0], srcA);
                float x1A = __shfl_sync(0xffffffffu, s0[1], srcA);
                float x0B = __shfl_sync(0xffffffffu, s0[0], srcB);
                float x1B = __shfl_sync(0xffffffffu, s0[1], srcB);
                aA[0] = __float_as_uint(odd ? x1A : x0A);
                aA[2] = __float_as_uint(odd ? x1B : x0B);
                float y0A = __shfl_sync(0xffffffffu, s0[2], srcA);
                float y1A = __shfl_sync(0xffffffffu, s0[3], srcA);
                float y0B = __shfl_sync(0xffffffffu, s0[2], srcB);
                float y1B = __shfl_sync(0xffffffffu, s0[3], srcB);
                aA[1] = __float_as_uint(odd ? y1A : y0A);
                aA[3] = __float_as_uint(odd ? y1B : y0B);
            }
            {
                float x0A = __shfl_sync(0xffffffffu, s1[0], srcA);
                float x1A = __shfl_sync(0xffffffffu, s1[1], srcA);
                float x0B = __shfl_sync(0xffffffffu, s1[0], srcB);
                float x1B = __shfl_sync(0xffffffffu, s1[1], srcB);
                aB[0] = __float_as_uint(odd ? x1A : x0A);
                aB[2] = __float_as_uint(odd ? x1B : x0B);
                float y0A = __shfl_sync(0xffffffffu, s1[2], srcA);
                float y1A = __shfl_sync(0xffffffffu, s1[3], srcA);
                float y0B = __shfl_sync(0xffffffffu, s1[2], srcB);
                float y1B = __shfl_sync(0xffffffffu, s1[3], srcB);
                aB[1] = __float_as_uint(odd ? y1A : y0A);
                aB[3] = __float_as_uint(odd ? y1B : y0B);
            }

            // PV: keys j*8..j*8+7 against all 64 d-columns
            #pragma unroll
            for (int jn = 0; jn < 8; jn++) {
                int dcol = jn * 8 + g;
                uint32_t b0 = __float_as_uint(Vb[(j * 8 + t)     * VSTR + dcol]);
                uint32_t b1 = __float_as_uint(Vb[(j * 8 + t + 4) * VSTR + dcol]);
                mma_tf32(oaccA[jn], aA, b0, b1);
                mma_tf32(oaccB[jn], aB, b0, b1);
            }
        }
    }

    // Row sums: reduce over the quad
    rsA0 += __shfl_xor_sync(0xffffffffu, rsA0, 1);
    rsA0 += __shfl_xor_sync(0xffffffffu, rsA0, 2);
    rsA1 += __shfl_xor_sync(0xffffffffu, rsA1, 1);
    rsA1 += __shfl_xor_sync(0xffffffffu, rsA1, 2);
    rsB0 += __shfl_xor_sync(0xffffffffu, rsB0, 1);
    rsB0 += __shfl_xor_sync(0xffffffffu, rsB0, 2);
    rsB1 += __shfl_xor_sync(0xffffffffu, rsB1, 1);
    rsB1 += __shfl_xor_sync(0xffffffffu, rsB1, 2);
    float invA0 = 1.0f / (rsA0 + 1e-8f);
    float invA1 = 1.0f / (rsA1 + 1e-8f);
    float invB0 = 1.0f / (rsB0 + 1e-8f);
    float invB1 = 1.0f / (rsB1 + 1e-8f);

    // Write O: out[b, q0+row, h*64 + col]
    #pragma unroll
    for (int jn = 0; jn < 8; jn++) {
        int dcol = jn * 8 + 2 * t;
        float* base = out + ((size_t)(b * SEQ + q0 + row0 + g)) * DMODEL + h * DK + dcol;
        *reinterpret_cast<float2*>(base) =
            make_float2(oaccA[jn][0] * invA0, oaccA[jn][1] * invA0);
        *reinterpret_cast<float2*>(base + (size_t)8 * DMODEL) =
            make_float2(oaccA[jn][2] * invA1, oaccA[jn][3] * invA1);
        *reinterpret_cast<float2*>(base + (size_t)16 * DMODEL) =
            make_float2(oaccB[jn][0] * invB0, oaccB[jn][1] * invB0);
        *reinterpret_cast<float2*>(base + (size_t)24 * DMODEL) =
            make_float2(oaccB[jn][2] * invB1, oaccB[jn][3] * invB1);
    }
}

// ---------------------------------------------------------------------------
extern "C" void kernel_launch(void* const* d_in, const int* in_sizes, int n_in,
                              void* d_out, int out_size)
{
    const float* x  = (const float*)d_in[0];
    const float* Wq = (const float*)d_in[1];
    const float* bq = (const float*)d_in[2];
    const float* Wk = (const float*)d_in[3];
    const float* bk = (const float*)d_in[4];
    const float* Wv = (const float*)d_in[5];
    const float* bv = (const float*)d_in[6];
    float* out = (float*)d_out;

    cudaFuncSetAttribute(attn_kernel, cudaFuncAttributeMaxDynamicSharedMemorySize,
                         (int)ATTN_SMEM_BYTES);
    cudaFuncSetAttribute(qkv_gemm_kernel, cudaFuncAttributeMaxDynamicSharedMemorySize,
                         (int)GEMM_SMEM_BYTES);

    float* gx; cudaGetSymbolAddress((void**)&gx, g_X);
    float* gw; cudaGetSymbolAddress((void**)&gw, g_W);
    const int xn4 = MTOT * DMODEL / 4;
    const int wn4 = DMODEL * DMODEL / 4;
    round_copy<<<(xn4 + 255) / 256, 256>>>(x, gx, xn4);
    dim3 wgrid((wn4 + 255) / 256, 3);
    round_copy_w<<<wgrid, 256>>>(Wq, Wk, Wv, gw, wn4);

    dim3 gemm_grid(DMODEL / BN, MTOT / BM, 3);   // 8 x 16 x 3
    qkv_gemm_kernel<<<gemm_grid, 256, GEMM_SMEM_BYTES>>>(bq, bk, bv);

    dim3 attn_grid(SEQ / QT, BH);                // 8 x 32
    attn_kernel<<<attn_grid, 256, ATTN_SMEM_BYTES>>>(out);
}

// round 11
// speedup vs baseline: 3.4073x; 1.1220x over previous
#include <cuda_runtime.h>
#include <cuda_bf16.h>
#include <cstdint>

// Problem constants
#define BATCH   2
#define SEQ     2048
#define DMODEL  1024
#define NHEADS  16
#define DK      64
#define BH      (BATCH * NHEADS)          // 32
#define MTOT    (BATCH * SEQ)             // 4096

// Scratch.
// g_X: fragment-quad layout: [m_blk(256)][k_blk(128)][lane(32)][4 floats]
//      lane=(g*4+t): {X[16mb+g][8kb+t], X[16mb+g+8][8kb+t], X[..g][..t+4], X[..g+8][..t+4]}
// g_W: k-pair layout per matrix: [k_blk(128)][n(1024)][t(4)] pairs {W[8kb+t][n], W[8kb+t+4][n]}
// g_Q: standard [bh][s][d]
// g_K: per row s: 32 pairs: float off = ((d>>3)*4 + (d&3))*2 + ((d&7)>>2)
// g_V: [s_blk(256)][d(64)][t(4)] pairs {V[8sb+t][d], V[8sb+t+4][d]}
__device__ float g_X[(size_t)MTOT * DMODEL];
__device__ float g_W[(size_t)3 * DMODEL * DMODEL];
__device__ float g_Q[(size_t)BH * SEQ * DK];
__device__ float g_K[(size_t)BH * SEQ * DK];
__device__ float g_V[(size_t)BH * SEQ * DK];

// ---------------------------------------------------------------------------
// Helpers
// ---------------------------------------------------------------------------
__device__ __forceinline__ float to_tf32(float x) {
    uint32_t u;
    asm("cvt.rna.tf32.f32 %0, %1;" : "=r"(u) : "f"(x));
    return __uint_as_float(u);
}

__device__ __forceinline__ float ex2f(float x) {
    float r;
    asm("ex2.approx.f32 %0, %1;" : "=f"(r) : "f"(x));
    return r;
}

__device__ __forceinline__ void mma_tf32(float c[4], const uint32_t a[4],
                                         uint32_t b0, uint32_t b1) {
    asm volatile(
        "mma.sync.aligned.m16n8k8.row.col.f32.tf32.tf32.f32 "
        "{%0,%1,%2,%3}, {%4,%5,%6,%7}, {%8,%9}, {%0,%1,%2,%3};"
        : "+f"(c[0]), "+f"(c[1]), "+f"(c[2]), "+f"(c[3])
        : "r"(a[0]), "r"(a[1]), "r"(a[2]), "r"(a[3]), "r"(b0), "r"(b1));
}

__device__ __forceinline__ void cp16(void* s, const void* gp) {
    uint32_t sa = (uint32_t)__cvta_generic_to_shared(s);
    asm volatile("cp.async.cg.shared.global [%0], [%1], 16;" :: "r"(sa), "l"(gp));
}
__device__ __forceinline__ void cp_commit() {
    asm volatile("cp.async.commit_group;");
}
__device__ __forceinline__ void cp_wait_all() {
    asm volatile("cp.async.wait_group 0;");
}

// ---------------------------------------------------------------------------
// Kernel 0a: X -> fragment-quad layout (tf32 pre-rounded)
// ---------------------------------------------------------------------------
__global__ void perm_x(const float* __restrict__ X)
{
    int i = blockIdx.x * blockDim.x + threadIdx.x;   // 1048576 threads
    int lane = i & 31;
    int t = lane & 3, g = lane >> 2;
    int kb = (i >> 5) & 127;
    int mb = i >> 12;
    const float* s = X + (size_t)(mb * 16) * DMODEL + kb * 8;
    float4 v;
    v.x = to_tf32(s[(size_t)g * DMODEL + t]);
    v.y = to_tf32(s[(size_t)(g + 8) * DMODEL + t]);
    v.z = to_tf32(s[(size_t)g * DMODEL + t + 4]);
    v.w = to_tf32(s[(size_t)(g + 8) * DMODEL + t + 4]);
    reinterpret_cast<float4*>(g_X)[i] = v;
}

// Kernel 0b: W -> k-pair layout (tf32 pre-rounded); blockIdx.y selects matrix
__global__ void perm_w(const float* __restrict__ w0,
                       const float* __restrict__ w1,
                       const float* __restrict__ w2)
{
    const float* src = (blockIdx.y == 0) ? w0 : (blockIdx.y == 1) ? w1 : w2;
    float* dst = g_W + (size_t)blockIdx.y * DMODEL * DMODEL;
    int i = blockIdx.x * blockDim.x + threadIdx.x;   // 524288 threads
    int t = i & 3;
    int n = (i >> 2) & 1023;
    int kb = i >> 12;
    float2 v;
    v.x = to_tf32(src[(size_t)(kb * 8 + t) * DMODEL + n]);
    v.y = to_tf32(src[(size_t)(kb * 8 + t + 4) * DMODEL + n]);
    reinterpret_cast<float2*>(dst)[i] = v;
}

// ---------------------------------------------------------------------------
// Kernel 1: QKV projection GEMM with fragment-native smem layouts.
// BM=256, BN=128, BK=32. 8 warps as 4x2 (warp tile 64x64).
// A: LDS.128 per (fm,ks); B: LDS.64 per (fn,ks).
// Epilogue writes Q standard (+log2e/8 scale), K pair rows, V pair-transposed.
// ---------------------------------------------------------------------------
#define BM 256
#define BN 128
#define BK 32
// smem (floats): A buf = 16 mb * 4 kb * 32 lanes * 4 = 8192; B buf = 4 kb * 128 n * 4 t * 2 = 4096
#define GEMM_SMEM_FLOATS (2 * 8192 + 2 * 4096)
#define GEMM_SMEM_BYTES  (GEMM_SMEM_FLOATS * sizeof(float))
#define NKTILES (DMODEL / BK)
#define QSCALE  0.18033688011112042f   // 0.125 * log2(e)

__global__ __launch_bounds__(256, 1)
void qkv_gemm_kernel(const float* __restrict__ bq,
                     const float* __restrict__ bk,
                     const float* __restrict__ bv)
{
    extern __shared__ float sg[];
    float* As = sg;                    // 2 bufs of 8192
    float* Bs = sg + 2 * 8192;         // 2 bufs of 4096

    const float* Wp;
    const float* bias;
    if (blockIdx.z == 0)      { Wp = g_W;                               bias = bq; }
    else if (blockIdx.z == 1) { Wp = g_W + (size_t)DMODEL * DMODEL;     bias = bk; }
    else                      { Wp = g_W + (size_t)2 * DMODEL * DMODEL; bias = bv; }

    const int m0 = blockIdx.y * BM;
    const int n0 = blockIdx.x * BN;
    const int tid  = threadIdx.x;
    const int lane = tid & 31;
    const int warp = tid >> 5;
    const int g = lane >> 2;
    const int t = lane & 3;
    const int wm = warp >> 1;     // 0..3 -> rows 64*wm
    const int wn = warp & 1;      // 0..1 -> cols 64*wn

    const int m0b = m0 >> 4;      // base m_blk
    const int n0q = n0;           // base n (global) for B

    // loader: A chunks 2048 (8/thr), B chunks 1024 (4/thr)
    auto load_ktile = [&](int kt, int buf) {
        float* Ab = As + buf * 8192;
        float* Bb = Bs + buf * 4096;
        const int k0b = kt * 4;    // 4 k_blks per BK tile
        #pragma unroll
        for (int it = 0; it < 8; it++) {
            int idx = tid + it * 256;
            int ch = idx & 31;
            int kb = (idx >> 5) & 3;
            int mb = idx >> 7;
            const float* src = g_X + (((size_t)(m0b + mb) * 128 + (k0b + kb)) * 32 + ch) * 4;
            cp16(Ab + ((mb * 4 + kb) * 32 + ch) * 4, src);
        }
        #pragma unroll
        for (int it = 0; it < 4; it++) {
            int idx = tid + it * 256;
            int kb = idx >> 8;
            int rest = idx & 255;
            const float* src = Wp + ((size_t)(k0b + kb) * DMODEL + n0q) * 8 + rest * 4;
            cp16(Bb + (kb * 1024 + rest * 4), src);
        }
        cp_commit();
    };

    load_ktile(0, 0);

    float acc[4][8][4];
    #pragma unroll
    for (int fm = 0; fm < 4; fm++)
        #pragma unroll
        for (int fn = 0; fn < 8; fn++)
            #pragma unroll
            for (int e = 0; e < 4; e++) acc[fm][fn][e] = 0.0f;

    for (int kt = 0; kt < NKTILES; kt++) {
        const int buf = kt & 1;
        cp_wait_all();
        __syncthreads();

        if (kt + 1 < NKTILES) load_ktile(kt + 1, buf ^ 1);

        const float* Ab = As + buf * 8192;
        const float* Bb = Bs + buf * 4096;

        #pragma unroll
        for (int ks = 0; ks < 4; ks++) {
            uint32_t a[4][4];
            #pragma unroll
            for (int fm = 0; fm < 4; fm++) {
                uint4 av = *reinterpret_cast<const uint4*>(
                    Ab + (((wm * 4 + fm) * 4 + ks) * 32 + lane) * 4);
                a[fm][0] = av.x; a[fm][1] = av.y; a[fm][2] = av.z; a[fm][3] = av.w;
            }
            #pragma unroll
            for (int fn = 0; fn < 8; fn++) {
                float2 bp = *reinterpret_cast<const float2*>(
                    Bb + ks * 1024 + ((wn * 64 + fn * 8 + g) * 4 + t) * 2);
                uint32_t b0 = __float_as_uint(bp.x);
                uint32_t b1 = __float_as_uint(bp.y);
                #pragma unroll
                for (int fm = 0; fm < 4; fm++) mma_tf32(acc[fm][fn], a[fm], b0, b1);
            }
        }
        __syncthreads();
    }

    // Epilogue
    const int b  = m0 / SEQ;
    const int s0 = m0 % SEQ;
    const int h0 = n0 >> 6;

    if (blockIdx.z == 0) {
        // Q standard layout, scale folds 1/sqrt(dk) * log2(e)
        #pragma unroll
        for (int fm = 0; fm < 4; fm++) {
            int r0 = wm * 64 + fm * 16 + g;
            #pragma unroll
            for (int fn = 0; fn < 8; fn++) {
                int c = wn * 64 + fn * 8 + 2 * t;
                int h = h0 + (c >> 6);
                int cc = c & 63;
                float bv0 = bias[n0 + c];
                float bv1 = bias[n0 + c + 1];
                float* dstbase = g_Q + ((size_t)(b * NHEADS + h) * SEQ + s0) * DK + cc;
                float2 v0 = make_float2(to_tf32((acc[fm][fn][0] + bv0) * QSCALE),
                                        to_tf32((acc[fm][fn][1] + bv1) * QSCALE));
                float2 v1 = make_float2(to_tf32((acc[fm][fn][2] + bv0) * QSCALE),
                                        to_tf32((acc[fm][fn][3] + bv1) * QSCALE));
                *reinterpret_cast<float2*>(&dstbase[(size_t)(r0)     * DK]) = v0;
                *reinterpret_cast<float2*>(&dstbase[(size_t)(r0 + 8) * DK]) = v1;
            }
        }
    } else if (blockIdx.z == 1) {
        // K pair rows: float off = ((d>>3)*4 + (d&3))*2 + ((d&7)>>2)
        #pragma unroll
        for (int fm = 0; fm < 4; fm++) {
            int r0 = wm * 64 + fm * 16 + g;
            #pragma unroll
            for (int fn = 0; fn < 8; fn++) {
                int c = wn * 64 + fn * 8 + 2 * t;
                int h = h0 + (c >> 6);
                int cc = c & 63;
                int f0 = ((cc >> 3) * 4 + (cc & 3)) * 2 + ((cc & 7) >> 2);
                int cc1 = cc + 1;
                int f1 = ((cc1 >> 3) * 4 + (cc1 & 3)) * 2 + ((cc1 & 7) >> 2);
                float bv0 = bias[n0 + c];
                float bv1 = bias[n0 + c + 1];
                float* base = g_K + (size_t)(b * NHEADS + h) * SEQ * DK;
                float* row0 = base + (size_t)(s0 + r0) * DK;
                float* row1 = base + (size_t)(s0 + r0 + 8) * DK;
                row0[f0] = to_tf32(acc[fm][fn][0] + bv0);
                row0[f1] = to_tf32(acc[fm][fn][1] + bv1);
                row1[f0] = to_tf32(acc[fm][fn][2] + bv0);
                row1[f1] = to_tf32(acc[fm][fn][3] + bv1);
            }
        }
    } else {
        // V pair-transposed: float off = (((s>>3)*64 + d)*4 + (s&3))*2 + ((s>>2)&1)
        #pragma unroll
        for (int fm = 0; fm < 4; fm++) {
            int r0 = wm * 64 + fm * 16 + g;
            #pragma unroll
            for (int fn = 0; fn < 8; fn++) {
                int c = wn * 64 + fn * 8 + 2 * t;
                int h = h0 + (c >> 6);
                int cc = c & 63;
                float bv0 = bias[n0 + c];
                float bv1 = bias[n0 + c + 1];
                float* base = g_V + (size_t)(b * NHEADS + h) * SEQ * DK;
                int sA = s0 + r0;
                int sB = s0 + r0 + 8;
                size_t fA0 = (((size_t)(sA >> 3) * 64 + cc)     * 4 + (sA & 3)) * 2 + ((sA >> 2) & 1);
                size_t fA1 = (((size_t)(sA >> 3) * 64 + cc + 1) * 4 + (sA & 3)) * 2 + ((sA >> 2) & 1);
                size_t fB0 = (((size_t)(sB >> 3) * 64 + cc)     * 4 + (sB & 3)) * 2 + ((sB >> 2) & 1);
                size_t fB1 = (((size_t)(sB >> 3) * 64 + cc + 1) * 4 + (sB & 3)) * 2 + ((sB >> 2) & 1);
                base[fA0] = to_tf32(acc[fm][fn][0] + bv0);
                base[fA1] = to_tf32(acc[fm][fn][1] + bv1);
                base[fB0] = to_tf32(acc[fm][fn][2] + bv0);
                base[fB1] = to_tf32(acc[fm][fn][3] + bv1);
            }
        }
    }
}

// ---------------------------------------------------------------------------
// Kernel 2: flash attention, QT=256, 8 warps x 32 rows, pair-layout K/V
// (LDS.64 operand fetch), exp via bare ex2 (log2e folded into Q).
// ---------------------------------------------------------------------------
#define QT   256
#define KSTR 72                       // floats per K smem row (288B, conflict-free)
#define NKT  (SEQ / 64)

#define ATTN_SMEM_FLOATS (2 * 64 * KSTR + 2 * 4096)
#define ATTN_SMEM_BYTES  (ATTN_SMEM_FLOATS * sizeof(float))

__global__ __launch_bounds__(256, 1)
void attn_kernel(float* __restrict__ out)
{
    extern __shared__ float sm[];
    float* Ks = sm;                   // 2 bufs of 64 x KSTR
    float* Vs = sm + 2 * 64 * KSTR;   // 2 bufs of 4096 (pair-transposed tiles)

    const int bh = blockIdx.y;
    const int b  = bh >> 4;
    const int h  = bh & 15;
    const int q0 = blockIdx.x * QT;

    const float* Qp = g_Q + (size_t)bh * SEQ * DK + (size_t)q0 * DK;
    const float* Kp = g_K + (size_t)bh * SEQ * DK;
    const float* Vp = g_V + (size_t)bh * SEQ * DK;

    const int tid  = threadIdx.x;
    const int lane = tid & 31;
    const int warp = tid >> 5;        // 0..7 -> q rows warp*32
    const int g = lane >> 2;
    const int t = lane & 3;
    const int row0 = warp * 32;

    // Q fragments (g_Q standard layout), staged through smem in 2 passes
    uint32_t qfA[8][4], qfB[8][4];
    #pragma unroll
    for (int p = 0; p < 2; p++) {
        #pragma unroll
        for (int it = 0; it < 8; it++) {
            int idx = tid + it * 256;      // 2048 float4
            int r = idx >> 4, c4 = (idx & 15) * 4;
            *reinterpret_cast<float4*>(&sm[r * 68 + c4]) =
                *reinterpret_cast<const float4*>(&Qp[(size_t)(p * 128 + r) * DK + c4]);
        }
        __syncthreads();
        if ((row0 >> 7) == p) {
            int lr = row0 & 127;
            #pragma unroll
            for (int ks = 0; ks < 8; ks++) {
                qfA[ks][0] = __float_as_uint(sm[(lr + g)      * 68 + 8 * ks + t]);
                qfA[ks][1] = __float_as_uint(sm[(lr + g + 8)  * 68 + 8 * ks + t]);
                qfA[ks][2] = __float_as_uint(sm[(lr + g)      * 68 + 8 * ks + t + 4]);
                qfA[ks][3] = __float_as_uint(sm[(lr + g + 8)  * 68 + 8 * ks + t + 4]);
                qfB[ks][0] = __float_as_uint(sm[(lr + g + 16) * 68 + 8 * ks + t]);
                qfB[ks][1] = __float_as_uint(sm[(lr + g + 24) * 68 + 8 * ks + t]);
                qfB[ks][2] = __float_as_uint(sm[(lr + g + 16) * 68 + 8 * ks + t + 4]);
                qfB[ks][3] = __float_as_uint(sm[(lr + g + 24) * 68 + 8 * ks + t + 4]);
            }
        }
        __syncthreads();
    }

    // K/V tile loader: K rows 64x16 chunks (gmem row 64 floats -> smem stride KSTR),
    // V linear 1024 chunks.
    auto load_tile = [&](int kt, int buf) {
        float* Kb = Ks + buf * 64 * KSTR;
        float* Vb = Vs + buf * 4096;
        const float* kp = Kp + (size_t)kt * 64 * DK;
        const float* vp = Vp + (size_t)kt * 4096;
        #pragma unroll
        for (int it = 0; it < 4; it++) {
            int idx = tid + it * 256;
            int r = idx >> 4, ch = idx & 15;
            cp16(&Kb[r * KSTR + ch * 4], kp + (size_t)r * DK + ch * 4);
            cp16(&Vb[idx * 4], vp + (size_t)idx * 4);
        }
        cp_commit();
    };

    load_tile(0, 0);

    float oaccA[8][4], oaccB[8][4];
    #pragma unroll
    for (int jn = 0; jn < 8; jn++)
        #pragma unroll
        for (int e = 0; e < 4; e++) { oaccA[jn][e] = 0.0f; oaccB[jn][e] = 0.0f; }
    float rsA0 = 0.0f, rsA1 = 0.0f, rsB0 = 0.0f, rsB1 = 0.0f;

    const int srcA = (lane & 28) | (t >> 1);   // 4g + t/2
    const int srcB = srcA + 2;
    const bool odd = (t & 1);

    for (int kt = 0; kt < NKT; kt++) {
        const int buf = kt & 1;
        cp_wait_all();
        __syncthreads();

        if (kt + 1 < NKT) load_tile(kt + 1, buf ^ 1);

        const float* Kb = Ks + buf * 64 * KSTR;
        const float* Vb = Vs + buf * 4096;

        #pragma unroll
        for (int j = 0; j < 8; j++) {
            float s0[4] = {0.f, 0.f, 0.f, 0.f};
            float s1[4] = {0.f, 0.f, 0.f, 0.f};
            #pragma unroll
            for (int ks = 0; ks < 8; ks++) {
                int key = j * 8 + g;
                float2 kp2 = *reinterpret_cast<const float2*>(
                    &Kb[key * KSTR + ks * 8 + t * 2]);
                uint32_t b0 = __float_as_uint(kp2.x);
                uint32_t b1 = __float_as_uint(kp2.y);
                mma_tf32(s0, qfA[ks], b0, b1);
                mma_tf32(s1, qfB[ks], b0, b1);
            }

            // exp (scores already in log2 domain) + rowsums + tf32 round
            {
                float e0 = ex2f(s0[0]), e1 = ex2f(s0[1]);
                float e2 = ex2f(s0[2]), e3 = ex2f(s0[3]);
                rsA0 += e0 + e1; rsA1 += e2 + e3;
                s0[0] = to_tf32(e0); s0[1] = to_tf32(e1);
                s0[2] = to_tf32(e2); s0[3] = to_tf32(e3);
            }
            {
                float e0 = ex2f(s1[0]), e1 = ex2f(s1[1]);
                float e2 = ex2f(s1[2]), e3 = ex2f(s1[3]);
                rsB0 += e0 + e1; rsB1 += e2 + e3;
                s1[0] = to_tf32(e0); s1[1] = to_tf32(e1);
                s1[2] = to_tf32(e2); s1[3] = to_tf32(e3);
            }

            // accumulator -> A-fragment transpose via quad shuffles
            uint32_t aA[4], aB[4];
            {
                float x0A = __shfl_sync(0xffffffffu, s0[0], srcA);
                float x1A = __shfl_sync(0xffffffffu, s0[1], srcA);
                float x0B = __shfl_sync(0xffffffffu, s0[0], srcB);
                float x1B = __shfl_sync(0xffffffffu, s0[1], srcB);
                aA[0] = __float_as_uint(odd ? x1A : x0A);
                aA[2] = __float_as_uint(odd ? x1B : x0B);
                float y0A = __shfl_sync(0xffffffffu, s0[2], srcA);
                float y1A = __shfl_sync(0xffffffffu, s0[3], srcA);
                float y0B = __shfl_sync(0xffffffffu, s0[2], srcB);
                float y1B = __shfl_sync(0xffffffffu, s0[3], srcB);
                aA[1] = __float_as_uint(odd ? y1A : y0A);
                aA[3] = __float_as_uint(odd ? y1B : y0B);
            }
            {
                float x0A = __shfl_sync(0xffffffffu, s1[0], srcA);
                float x1A = __shfl_sync(0xffffffffu, s1[1], srcA);
                float x0B = __shfl_sync(0xffffffffu, s1[0], srcB);
                float x1B = __shfl_sync(0xffffffffu, s1[1], srcB);
                aB[0] = __float_as_uint(odd ? x1A : x0A);
                aB[2] = __float_as_uint(odd ? x1B : x0B);
                float y0A = __shfl_sync(0xffffffffu, s1[2], srcA);
                float y1A = __shfl_sync(0xffffffffu, s1[3], srcA);
                float y0B = __shfl_sync(0xffffffffu, s1[2], srcB);
                float y1B = __shfl_sync(0xffffffffu, s1[3], srcB);
                aB[1] = __float_as_uint(odd ? y1A : y0A);
                aB[3] = __float_as_uint(odd ? y1B : y0B);
            }

            // PV with pair-layout V: LDS.64 per (j, jn)
            #pragma unroll
            for (int jn = 0; jn < 8; jn++) {
                int dcol = jn * 8 + g;
                float2 vp2 = *reinterpret_cast<const float2*>(
                    &Vb[(j * 64 + dcol) * 8 + t * 2]);
                uint32_t b0 = __float_as_uint(vp2.x);
                uint32_t b1 = __float_as_uint(vp2.y);
                mma_tf32(oaccA[jn], aA, b0, b1);
                mma_tf32(oaccB[jn], aB, b0, b1);
            }
        }
    }

    rsA0 += __shfl_xor_sync(0xffffffffu, rsA0, 1);
    rsA0 += __shfl_xor_sync(0xffffffffu, rsA0, 2);
    rsA1 += __shfl_xor_sync(0xffffffffu, rsA1, 1);
    rsA1 += __shfl_xor_sync(0xffffffffu, rsA1, 2);
    rsB0 += __shfl_xor_sync(0xffffffffu, rsB0, 1);
    rsB0 += __shfl_xor_sync(0xffffffffu, rsB0, 2);
    rsB1 += __shfl_xor_sync(0xffffffffu, rsB1, 1);
    rsB1 += __shfl_xor_sync(0xffffffffu, rsB1, 2);
    float invA0 = 1.0f / (rsA0 + 1e-8f);
    float invA1 = 1.0f / (rsA1 + 1e-8f);
    float invB0 = 1.0f / (rsB0 + 1e-8f);
    float invB1 = 1.0f / (rsB1 + 1e-8f);

    #pragma unroll
    for (int jn = 0; jn < 8; jn++) {
        int dcol = jn * 8 + 2 * t;
        float* base = out + ((size_t)(b * SEQ + q0 + row0 + g)) * DMODEL + h * DK + dcol;
        *reinterpret_cast<float2*>(base) =
            make_float2(oaccA[jn][0] * invA0, oaccA[jn][1] * invA0);
        *reinterpret_cast<float2*>(base + (size_t)8 * DMODEL) =
            make_float2(oaccA[jn][2] * invA1, oaccA[jn][3] * invA1);
        *reinterpret_cast<float2*>(base + (size_t)16 * DMODEL) =
            make_float2(oaccB[jn][0] * invB0, oaccB[jn][1] * invB0);
        *reinterpret_cast<float2*>(base + (size_t)24 * DMODEL) =
            make_float2(oaccB[jn][2] * invB1, oaccB[jn][3] * invB1);
    }
}

// ---------------------------------------------------------------------------
extern "C" void kernel_launch(void* const* d_in, const int* in_sizes, int n_in,
                              void* d_out, int out_size)
{
    const float* x  = (const float*)d_in[0];
    const float* Wq = (const float*)d_in[1];
    const float* bq = (const float*)d_in[2];
    const float* Wk = (const float*)d_in[3];
    const float* bk = (const float*)d_in[4];
    const float* Wv = (const float*)d_in[5];
    const float* bv = (const float*)d_in[6];
    float* out = (float*)d_out;

    cudaFuncSetAttribute(attn_kernel, cudaFuncAttributeMaxDynamicSharedMemorySize,
                         (int)ATTN_SMEM_BYTES);
    cudaFuncSetAttribute(qkv_gemm_kernel, cudaFuncAttributeMaxDynamicSharedMemorySize,
                         (int)GEMM_SMEM_BYTES);

    perm_x<<<(MTOT / 16) * (DMODEL / 8) * 32 / 256, 256>>>(x);
    dim3 wgrid((DMODEL / 8) * DMODEL * 4 / 256, 3);
    perm_w<<<wgrid, 256>>>(Wq, Wk, Wv);

    dim3 gemm_grid(DMODEL / BN, MTOT / BM, 3);   // 8 x 16 x 3
    qkv_gemm_kernel<<<gemm_grid, 256, GEMM_SMEM_BYTES>>>(bq, bk, bv);

    dim3 attn_grid(SEQ / QT, BH);                // 8 x 32
    attn_kernel<<<attn_grid, 256, ATTN_SMEM_BYTES>>>(out);
}

// round 14
// speedup vs baseline: 4.0882x; 1.1998x over previous
#include <cuda_runtime.h>
#include <cuda_bf16.h>
#include <cuda_fp16.h>
#include <cstdint>

// Problem constants
#define BATCH   2
#define SEQ     2048
#define DMODEL  1024
#define NHEADS  16
#define DK      64
#define BH      (BATCH * NHEADS)          // 32
#define MTOT    (BATCH * SEQ)             // 4096

// Scratch layouts:
// g_X: fragment-quad: [m_blk(256)][k_blk(128)][lane(32)][4]
// g_W: k-pair per matrix: [k_blk(128)][n(1024)][t(4)] pairs {W[8kb+t][n], W[8kb+t+4][n]}
// g_Q: standard [bh][s][d] (scaled by 0.125*log2e, tf32)
// g_K: per row s: pair layout: float off = ((d>>3)*4 + (d&3))*2 + ((d&7)>>2) (tf32)
// g_V: fp16 (reinterpreted), per head: idx(s,d) = ((s>>4)*64+d)*16 + p*2 + (s&1),
//      where k2=(s&15)>>1, p = 2*(k2&3) + (k2>>2)  (pairs (t,t+4) adjacent for LDS.64)
__device__ float g_X[(size_t)MTOT * DMODEL];
__device__ float g_W[(size_t)3 * DMODEL * DMODEL];
__device__ float g_Q[(size_t)BH * SEQ * DK];
__device__ float g_K[(size_t)BH * SEQ * DK];
__device__ float g_V[(size_t)BH * SEQ * DK];     // used as fp16 (half occupied)

// ---------------------------------------------------------------------------
// Helpers
// ---------------------------------------------------------------------------
__device__ __forceinline__ float to_tf32(float x) {
    uint32_t u;
    asm("cvt.rna.tf32.f32 %0, %1;" : "=r"(u) : "f"(x));
    return __uint_as_float(u);
}

__device__ __forceinline__ float ex2f(float x) {
    float r;
    asm("ex2.approx.f32 %0, %1;" : "=f"(r) : "f"(x));
    return r;
}

__device__ __forceinline__ uint32_t pack_f16x2(float lo, float hi) {
    uint32_t r;
    asm("cvt.rn.f16x2.f32 %0, %1, %2;" : "=r"(r) : "f"(hi), "f"(lo));
    return r;
}

__device__ __forceinline__ void mma_tf32(float c[4], const uint32_t a[4],
                                         uint32_t b0, uint32_t b1) {
    asm volatile(
        "mma.sync.aligned.m16n8k8.row.col.f32.tf32.tf32.f32 "
        "{%0,%1,%2,%3}, {%4,%5,%6,%7}, {%8,%9}, {%0,%1,%2,%3};"
        : "+f"(c[0]), "+f"(c[1]), "+f"(c[2]), "+f"(c[3])
        : "r"(a[0]), "r"(a[1]), "r"(a[2]), "r"(a[3]), "r"(b0), "r"(b1));
}

__device__ __forceinline__ void mma_f16(float c[4], const uint32_t a[4],
                                        uint32_t b0, uint32_t b1) {
    asm volatile(
        "mma.sync.aligned.m16n8k16.row.col.f32.f16.f16.f32 "
        "{%0,%1,%2,%3}, {%4,%5,%6,%7}, {%8,%9}, {%0,%1,%2,%3};"
        : "+f"(c[0]), "+f"(c[1]), "+f"(c[2]), "+f"(c[3])
        : "r"(a[0]), "r"(a[1]), "r"(a[2]), "r"(a[3]), "r"(b0), "r"(b1));
}

__device__ __forceinline__ void cp16(void* s, const void* gp) {
    uint32_t sa = (uint32_t)__cvta_generic_to_shared(s);
    asm volatile("cp.async.cg.shared.global [%0], [%1], 16;" :: "r"(sa), "l"(gp));
}
__device__ __forceinline__ void cp_commit() {
    asm volatile("cp.async.commit_group;");
}
__device__ __forceinline__ void cp_wait_all() {
    asm volatile("cp.async.wait_group 0;");
}

// ---------------------------------------------------------------------------
// Kernel 0a: X -> fragment-quad layout (tf32 pre-rounded)
// ---------------------------------------------------------------------------
__global__ void perm_x(const float* __restrict__ X)
{
    int i = blockIdx.x * blockDim.x + threadIdx.x;
    int lane = i & 31;
    int t = lane & 3, g = lane >> 2;
    int kb = (i >> 5) & 127;
    int mb = i >> 12;
    const float* s = X + (size_t)(mb * 16) * DMODEL + kb * 8;
    float4 v;
    v.x = to_tf32(s[(size_t)g * DMODEL + t]);
    v.y = to_tf32(s[(size_t)(g + 8) * DMODEL + t]);
    v.z = to_tf32(s[(size_t)g * DMODEL + t + 4]);
    v.w = to_tf32(s[(size_t)(g + 8) * DMODEL + t + 4]);
    reinterpret_cast<float4*>(g_X)[i] = v;
}

// Kernel 0b: W -> k-pair layout (tf32 pre-rounded); blockIdx.y selects matrix
__global__ void perm_w(const float* __restrict__ w0,
                       const float* __restrict__ w1,
                       const float* __restrict__ w2)
{
    const float* src = (blockIdx.y == 0) ? w0 : (blockIdx.y == 1) ? w1 : w2;
    float* dst = g_W + (size_t)blockIdx.y * DMODEL * DMODEL;
    int i = blockIdx.x * blockDim.x + threadIdx.x;
    int t = i & 3;
    int n = (i >> 2) & 1023;
    int kb = i >> 12;
    float2 v;
    v.x = to_tf32(src[(size_t)(kb * 8 + t) * DMODEL + n]);
    v.y = to_tf32(src[(size_t)(kb * 8 + t + 4) * DMODEL + n]);
    reinterpret_cast<float2*>(dst)[i] = v;
}

// ---------------------------------------------------------------------------
// Kernel 1: QKV projection GEMM. Epilogue: Q std (+log2e/8), K pair rows
// (tf32), V fp16 pair-interleaved.
// ---------------------------------------------------------------------------
#define BM 256
#define BN 128
#define BK 32
#define GEMM_SMEM_FLOATS (2 * 8192 + 2 * 4096)
#define GEMM_SMEM_BYTES  (GEMM_SMEM_FLOATS * sizeof(float))
#define NKTILES (DMODEL / BK)
#define QSCALE  0.18033688011112042f   // 0.125 * log2(e)

__global__ __launch_bounds__(256, 1)
void qkv_gemm_kernel(const float* __restrict__ bq,
                     const float* __restrict__ bk,
                     const float* __restrict__ bv)
{
    extern __shared__ float sg[];
    float* As = sg;
    float* Bs = sg + 2 * 8192;

    const float* Wp;
    const float* bias;
    if (blockIdx.z == 0)      { Wp = g_W;                               bias = bq; }
    else if (blockIdx.z == 1) { Wp = g_W + (size_t)DMODEL * DMODEL;     bias = bk; }
    else                      { Wp = g_W + (size_t)2 * DMODEL * DMODEL; bias = bv; }

    const int m0 = blockIdx.y * BM;
    const int n0 = blockIdx.x * BN;
    const int tid  = threadIdx.x;
    const int lane = tid & 31;
    const int warp = tid >> 5;
    const int g = lane >> 2;
    const int t = lane & 3;
    const int wm = warp >> 1;
    const int wn = warp & 1;

    const int m0b = m0 >> 4;
    const int n0q = n0;

    auto load_ktile = [&](int kt, int buf) {
        float* Ab = As + buf * 8192;
        float* Bb = Bs + buf * 4096;
        const int k0b = kt * 4;
        #pragma unroll
        for (int it = 0; it < 8; it++) {
            int idx = tid + it * 256;
            int ch = idx & 31;
            int kb = (idx >> 5) & 3;
            int mb = idx >> 7;
            const float* src = g_X + (((size_t)(m0b + mb) * 128 + (k0b + kb)) * 32 + ch) * 4;
            cp16(Ab + ((mb * 4 + kb) * 32 + ch) * 4, src);
        }
        #pragma unroll
        for (int it = 0; it < 4; it++) {
            int idx = tid + it * 256;
            int kb = idx >> 8;
            int rest = idx & 255;
            const float* src = Wp + ((size_t)(k0b + kb) * DMODEL + n0q) * 8 + rest * 4;
            cp16(Bb + (kb * 1024 + rest * 4), src);
        }
        cp_commit();
    };

    load_ktile(0, 0);

    float acc[4][8][4];
    #pragma unroll
    for (int fm = 0; fm < 4; fm++)
        #pragma unroll
        for (int fn = 0; fn < 8; fn++)
            #pragma unroll
            for (int e = 0; e < 4; e++) acc[fm][fn][e] = 0.0f;

    for (int kt = 0; kt < NKTILES; kt++) {
        const int buf = kt & 1;
        cp_wait_all();
        __syncthreads();

        if (kt + 1 < NKTILES) load_ktile(kt + 1, buf ^ 1);

        const float* Ab = As + buf * 8192;
        const float* Bb = Bs + buf * 4096;

        #pragma unroll
        for (int ks = 0; ks < 4; ks++) {
            uint32_t a[4][4];
            #pragma unroll
            for (int fm = 0; fm < 4; fm++) {
                uint4 av = *reinterpret_cast<const uint4*>(
                    Ab + (((wm * 4 + fm) * 4 + ks) * 32 + lane) * 4);
                a[fm][0] = av.x; a[fm][1] = av.y; a[fm][2] = av.z; a[fm][3] = av.w;
            }
            #pragma unroll
            for (int fn = 0; fn < 8; fn++) {
                float2 bp = *reinterpret_cast<const float2*>(
                    Bb + ks * 1024 + ((wn * 64 + fn * 8 + g) * 4 + t) * 2);
                uint32_t b0 = __float_as_uint(bp.x);
                uint32_t b1 = __float_as_uint(bp.y);
                #pragma unroll
                for (int fm = 0; fm < 4; fm++) mma_tf32(acc[fm][fn], a[fm], b0, b1);
            }
        }
        __syncthreads();
    }

    const int b  = m0 / SEQ;
    const int s0 = m0 % SEQ;
    const int h0 = n0 >> 6;

    if (blockIdx.z == 0) {
        #pragma unroll
        for (int fm = 0; fm < 4; fm++) {
            int r0 = wm * 64 + fm * 16 + g;
            #pragma unroll
            for (int fn = 0; fn < 8; fn++) {
                int c = wn * 64 + fn * 8 + 2 * t;
                int h = h0 + (c >> 6);
                int cc = c & 63;
                float bv0 = bias[n0 + c];
                float bv1 = bias[n0 + c + 1];
                float* dstbase = g_Q + ((size_t)(b * NHEADS + h) * SEQ + s0) * DK + cc;
                float2 v0 = make_float2(to_tf32((acc[fm][fn][0] + bv0) * QSCALE),
                                        to_tf32((acc[fm][fn][1] + bv1) * QSCALE));
                float2 v1 = make_float2(to_tf32((acc[fm][fn][2] + bv0) * QSCALE),
                                        to_tf32((acc[fm][fn][3] + bv1) * QSCALE));
                *reinterpret_cast<float2*>(&dstbase[(size_t)(r0)     * DK]) = v0;
                *reinterpret_cast<float2*>(&dstbase[(size_t)(r0 + 8) * DK]) = v1;
            }
        }
    } else if (blockIdx.z == 1) {
        #pragma unroll
        for (int fm = 0; fm < 4; fm++) {
            int r0 = wm * 64 + fm * 16 + g;
            #pragma unroll
            for (int fn = 0; fn < 8; fn++) {
                int c = wn * 64 + fn * 8 + 2 * t;
                int h = h0 + (c >> 6);
                int cc = c & 63;
                int f0 = ((cc >> 3) * 4 + (cc & 3)) * 2 + ((cc & 7) >> 2);
                int cc1 = cc + 1;
                int f1 = ((cc1 >> 3) * 4 + (cc1 & 3)) * 2 + ((cc1 & 7) >> 2);
                float bv0 = bias[n0 + c];
                float bv1 = bias[n0 + c + 1];
                float* base = g_K + (size_t)(b * NHEADS + h) * SEQ * DK;
                float* row0 = base + (size_t)(s0 + r0) * DK;
                float* row1 = base + (size_t)(s0 + r0 + 8) * DK;
                row0[f0] = to_tf32(acc[fm][fn][0] + bv0);
                row0[f1] = to_tf32(acc[fm][fn][1] + bv1);
                row1[f0] = to_tf32(acc[fm][fn][2] + bv0);
                row1[f1] = to_tf32(acc[fm][fn][3] + bv1);
            }
        }
    } else {
        // V fp16 pair-interleaved: idx(s,d) = ((s>>4)*64+d)*16 + p*2 + (s&1),
        // k2=(s&15)>>1, p = 2*(k2&3) + (k2>>2)
        __half* gV = reinterpret_cast<__half*>(g_V);
        #pragma unroll
        for (int fm = 0; fm < 4; fm++) {
            int r0 = wm * 64 + fm * 16 + g;
            #pragma unroll
            for (int fn = 0; fn < 8; fn++) {
                int c = wn * 64 + fn * 8 + 2 * t;
                int h = h0 + (c >> 6);
                int cc = c & 63;
                float bv0 = bias[n0 + c];
                float bv1 = bias[n0 + c + 1];
                __half* base = gV + (size_t)(b * NHEADS + h) * SEQ * DK;
                int sA = s0 + r0;
                int sB = sA + 8;
                int k2A = (sA & 15) >> 1, pA = 2 * (k2A & 3) + (k2A >> 2);
                int k2B = (sB & 15) >> 1, pB = 2 * (k2B & 3) + (k2B >> 2);
                size_t gA = ((size_t)(sA >> 4) * 64) * 16 + pA * 2 + (sA & 1);
                size_t gB = ((size_t)(sB >> 4) * 64) * 16 + pB * 2 + (sB & 1);
                base[gA + (size_t)cc * 16]       = __float2half(acc[fm][fn][0] + bv0);
                base[gA + (size_t)(cc + 1) * 16] = __float2half(acc[fm][fn][1] + bv1);
                base[gB + (size_t)cc * 16]       = __float2half(acc[fm][fn][2] + bv0);
                base[gB + (size_t)(cc + 1) * 16] = __float2half(acc[fm][fn][3] + bv1);
            }
        }
    }
}

// ---------------------------------------------------------------------------
// Kernel 2: flash attention, QT=256, 8 warps x 32 rows. QK^T tf32 (pair K),
// P packed to fp16x2 directly from accumulators (NO shuffles), PV fp16
// m16n8k16 with pair-interleaved fp16 V (LDS.64 per operand), fp32 accum.
// ---------------------------------------------------------------------------
#define QT   256
#define KSTR 72
#define NKT  (SEQ / 64)

// K: 2 bufs x 64 x KSTR floats; V: 2 bufs x 2048 uint32 (f16x2)
#define ATTN_SMEM_FLOATS (2 * 64 * KSTR + 2 * 2048)
#define ATTN_SMEM_BYTES  (ATTN_SMEM_FLOATS * sizeof(float))

__global__ __launch_bounds__(256, 1)
void attn_kernel(float* __restrict__ out)
{
    extern __shared__ float sm[];
    float* Ks = sm;                                            // 2 x 64 x KSTR
    uint32_t* Vs = reinterpret_cast<uint32_t*>(sm + 2 * 64 * KSTR);  // 2 x 2048

    const int bh = blockIdx.y;
    const int b  = bh >> 4;
    const int h  = bh & 15;
    const int q0 = blockIdx.x * QT;

    const float* Qp = g_Q + (size_t)bh * SEQ * DK + (size_t)q0 * DK;
    const float* Kp = g_K + (size_t)bh * SEQ * DK;
    const __half* Vp = reinterpret_cast<const __half*>(g_V) + (size_t)bh * SEQ * DK;

    const int tid  = threadIdx.x;
    const int lane = tid & 31;
    const int warp = tid >> 5;
    const int g = lane >> 2;
    const int t = lane & 3;
    const int row0 = warp * 32;

    // Q fragments staged through smem in 2 passes
    uint32_t qfA[8][4], qfB[8][4];
    #pragma unroll
    for (int p = 0; p < 2; p++) {
        #pragma unroll
        for (int it = 0; it < 8; it++) {
            int idx = tid + it * 256;
            int r = idx >> 4, c4 = (idx & 15) * 4;
            *reinterpret_cast<float4*>(&sm[r * 68 + c4]) =
                *reinterpret_cast<const float4*>(&Qp[(size_t)(p * 128 + r) * DK + c4]);
        }
        __syncthreads();
        if ((row0 >> 7) == p) {
            int lr = row0 & 127;
            #pragma unroll
            for (int ks = 0; ks < 8; ks++) {
                qfA[ks][0] = __float_as_uint(sm[(lr + g)      * 68 + 8 * ks + t]);
                qfA[ks][1] = __float_as_uint(sm[(lr + g + 8)  * 68 + 8 * ks + t]);
                qfA[ks][2] = __float_as_uint(sm[(lr + g)      * 68 + 8 * ks + t + 4]);
                qfA[ks][3] = __float_as_uint(sm[(lr + g + 8)  * 68 + 8 * ks + t + 4]);
                qfB[ks][0] = __float_as_uint(sm[(lr + g + 16) * 68 + 8 * ks + t]);
                qfB[ks][1] = __float_as_uint(sm[(lr + g + 24) * 68 + 8 * ks + t]);
                qfB[ks][2] = __float_as_uint(sm[(lr + g + 16) * 68 + 8 * ks + t + 4]);
                qfB[ks][3] = __float_as_uint(sm[(lr + g + 24) * 68 + 8 * ks + t + 4]);
            }
        }
        __syncthreads();
    }

    // Tile loader: K = 1024 x 16B, V = 512 x 16B (fp16 tile is 8KB)
    auto load_tile = [&](int kt, int buf) {
        float* Kb = Ks + buf * 64 * KSTR;
        uint32_t* Vb = Vs + buf * 2048;
        const float* kp = Kp + (size_t)kt * 64 * DK;
        const char* vp = reinterpret_cast<const char*>(Vp) + (size_t)kt * 8192;
        #pragma unroll
        for (int it = 0; it < 4; it++) {
            int idx = tid + it * 256;
            int r = idx >> 4, ch = idx & 15;
            cp16(&Kb[r * KSTR + ch * 4], kp + (size_t)r * DK + ch * 4);
        }
        #pragma unroll
        for (int it = 0; it < 2; it++) {
            int idx = tid + it * 256;
            cp16(&Vb[idx * 4], vp + (size_t)idx * 16);
        }
        cp_commit();
    };

    load_tile(0, 0);

    float oaccA[8][4], oaccB[8][4];
    #pragma unroll
    for (int jn = 0; jn < 8; jn++)
        #pragma unroll
        for (int e = 0; e < 4; e++) { oaccA[jn][e] = 0.0f; oaccB[jn][e] = 0.0f; }
    float rsA0 = 0.0f, rsA1 = 0.0f, rsB0 = 0.0f, rsB1 = 0.0f;

    for (int kt = 0; kt < NKT; kt++) {
        const int buf = kt & 1;
        cp_wait_all();
        __syncthreads();

        if (kt + 1 < NKT) load_tile(kt + 1, buf ^ 1);

        const float* Kb = Ks + buf * 64 * KSTR;
        const uint32_t* Vb = Vs + buf * 2048;

        #pragma unroll
        for (int j2 = 0; j2 < 4; j2++) {
            // S for keys j2*16 .. j2*16+15 (even 8-group E, odd 8-group O)
            float sEA[4] = {0.f,0.f,0.f,0.f}, sEB[4] = {0.f,0.f,0.f,0.f};
            float sOA[4] = {0.f,0.f,0.f,0.f}, sOB[4] = {0.f,0.f,0.f,0.f};
            #pragma unroll
            for (int ks = 0; ks < 8; ks++) {
                int keyE = j2 * 16 + g;
                int keyO = keyE + 8;
                float2 kE = *reinterpret_cast<const float2*>(&Kb[keyE * KSTR + ks * 8 + t * 2]);
                float2 kO = *reinterpret_cast<const float2*>(&Kb[keyO * KSTR + ks * 8 + t * 2]);
                uint32_t e0 = __float_as_uint(kE.x), e1 = __float_as_uint(kE.y);
                uint32_t o0 = __float_as_uint(kO.x), o1 = __float_as_uint(kO.y);
                mma_tf32(sEA, qfA[ks], e0, e1);
                mma_tf32(sEB, qfB[ks], e0, e1);
                mma_tf32(sOA, qfA[ks], o0, o1);
                mma_tf32(sOB, qfB[ks], o0, o1);
            }

            // exp2 (scores in log2 domain), rowsums, pack to fp16 A-fragments
            uint32_t aA[4], aB[4];
            {
                float e0 = ex2f(sEA[0]), e1 = ex2f(sEA[1]);
                float e2 = ex2f(sEA[2]), e3 = ex2f(sEA[3]);
                float o0 = ex2f(sOA[0]), o1 = ex2f(sOA[1]);
                float o2 = ex2f(sOA[2]), o3 = ex2f(sOA[3]);
                rsA0 += e0 + e1 + o0 + o1;
                rsA1 += e2 + e3 + o2 + o3;
                aA[0] = pack_f16x2(e0, e1);
                aA[1] = pack_f16x2(e2, e3);
                aA[2] = pack_f16x2(o0, o1);
                aA[3] = pack_f16x2(o2, o3);
            }
            {
                float e0 = ex2f(sEB[0]), e1 = ex2f(sEB[1]);
                float e2 = ex2f(sEB[2]), e3 = ex2f(sEB[3]);
                float o0 = ex2f(sOB[0]), o1 = ex2f(sOB[1]);
                float o2 = ex2f(sOB[2]), o3 = ex2f(sOB[3]);
                rsB0 += e0 + e1 + o0 + o1;
                rsB1 += e2 + e3 + o2 + o3;
                aB[0] = pack_f16x2(e0, e1);
                aB[1] = pack_f16x2(e2, e3);
                aB[2] = pack_f16x2(o0, o1);
                aB[3] = pack_f16x2(o2, o3);
            }

            // PV: m16n8k16 fp16 (fp32 accum), V pair-interleaved (LDS.64)
            #pragma unroll
            for (int jn = 0; jn < 8; jn++) {
                int dcol = jn * 8 + g;
                uint2 bv = *reinterpret_cast<const uint2*>(
                    &Vb[(j2 * 64 + dcol) * 8 + 2 * t]);
                mma_f16(oaccA[jn], aA, bv.x, bv.y);
                mma_f16(oaccB[jn], aB, bv.x, bv.y);
            }
        }
    }

    rsA0 += __shfl_xor_sync(0xffffffffu, rsA0, 1);
    rsA0 += __shfl_xor_sync(0xffffffffu, rsA0, 2);
    rsA1 += __shfl_xor_sync(0xffffffffu, rsA1, 1);
    rsA1 += __shfl_xor_sync(0xffffffffu, rsA1, 2);
    rsB0 += __shfl_xor_sync(0xffffffffu, rsB0, 1);
    rsB0 += __shfl_xor_sync(0xffffffffu, rsB0, 2);
    rsB1 += __shfl_xor_sync(0xffffffffu, rsB1, 1);
    rsB1 += __shfl_xor_sync(0xffffffffu, rsB1, 2);
    float invA0 = 1.0f / (rsA0 + 1e-8f);
    float invA1 = 1.0f / (rsA1 + 1e-8f);
    float invB0 = 1.0f / (rsB0 + 1e-8f);
    float invB1 = 1.0f / (rsB1 + 1e-8f);

    #pragma unroll
    for (int jn = 0; jn < 8; jn++) {
        int dcol = jn * 8 + 2 * t;
        float* base = out + ((size_t)(b * SEQ + q0 + row0 + g)) * DMODEL + h * DK + dcol;
        *reinterpret_cast<float2*>(base) =
            make_float2(oaccA[jn][0] * invA0, oaccA[jn][1] * invA0);
        *reinterpret_cast<float2*>(base + (size_t)8 * DMODEL) =
            make_float2(oaccA[jn][2] * invA1, oaccA[jn][3] * invA1);
        *reinterpret_cast<float2*>(base + (size_t)16 * DMODEL) =
            make_float2(oaccB[jn][0] * invB0, oaccB[jn][1] * invB0);
        *reinterpret_cast<float2*>(base + (size_t)24 * DMODEL) =
            make_float2(oaccB[jn][2] * invB1, oaccB[jn][3] * invB1);
    }
}

// ---------------------------------------------------------------------------
extern "C" void kernel_launch(void* const* d_in, const int* in_sizes, int n_in,
                              void* d_out, int out_size)
{
    const float* x  = (const float*)d_in[0];
    const float* Wq = (const float*)d_in[1];
    const float* bq = (const float*)d_in[2];
    const float* Wk = (const float*)d_in[3];
    const float* bk = (const float*)d_in[4];
    const float* Wv = (const float*)d_in[5];
    const float* bv = (const float*)d_in[6];
    float* out = (float*)d_out;

    cudaFuncSetAttribute(attn_kernel, cudaFuncAttributeMaxDynamicSharedMemorySize,
                         (int)ATTN_SMEM_BYTES);
    cudaFuncSetAttribute(qkv_gemm_kernel, cudaFuncAttributeMaxDynamicSharedMemorySize,
                         (int)GEMM_SMEM_BYTES);

    perm_x<<<(MTOT / 16) * (DMODEL / 8) * 32 / 256, 256>>>(x);
    dim3 wgrid((DMODEL / 8) * DMODEL * 4 / 256, 3);
    perm_w<<<wgrid, 256>>>(Wq, Wk, Wv);

    dim3 gemm_grid(DMODEL / BN, MTOT / BM, 3);   // 8 x 16 x 3
    qkv_gemm_kernel<<<gemm_grid, 256, GEMM_SMEM_BYTES>>>(bq, bk, bv);

    dim3 attn_grid(SEQ / QT, BH);                // 8 x 32
    attn_kernel<<<attn_grid, 256, ATTN_SMEM_BYTES>>>(out);
}

// round 15
// speedup vs baseline: 5.8103x; 1.4212x over previous
#include <cuda_runtime.h>
#include <cuda_bf16.h>
#include <cuda_fp16.h>
#include <cstdint>

// Problem constants
#define BATCH   2
#define SEQ     2048
#define DMODEL  1024
#define NHEADS  16
#define DK      64
#define BH      (BATCH * NHEADS)          // 32
#define MTOT    (BATCH * SEQ)             // 4096

// Scratch (declared as float arrays; used as fp16 payloads):
// g_X (fp16, uint4 units): [m_blk(256)][k_blk(64)][lane(32)] -> 4 uint32:
//   a0={X[16mb+g][16kb+2t],+1}, a1={row g+8 same}, a2={X[g][16kb+2t+8],+9}, a3={row g+8}
// g_W (fp16, uint2 units) per matrix: [kb(64)][n(1024)][t(4)]:
//   r0={W[16kb+2t][n],W[16kb+2t+1][n]}, r1={W[16kb+2t+8][n],+9}
// g_Q, g_K (fp16, 32 uint32 per row s): pair layout:
//   d pair j=(d&15)>>1 of block kb=d>>4 stored at uint32 idx = kb*8 + 2*(j&3) + (j>>2)
// g_V (fp16): idx(s,d) = ((s>>4)*64+d)*16 + p*2 + (s&1), k2=(s&15)>>1, p=2*(k2&3)+(k2>>2)
__device__ float g_X[(size_t)MTOT * DMODEL];
__device__ float g_W[(size_t)3 * DMODEL * DMODEL];
__device__ float g_Q[(size_t)BH * SEQ * DK];
__device__ float g_K[(size_t)BH * SEQ * DK];
__device__ float g_V[(size_t)BH * SEQ * DK];

// ---------------------------------------------------------------------------
// Helpers
// ---------------------------------------------------------------------------
__device__ __forceinline__ float ex2f(float x) {
    float r;
    asm("ex2.approx.f32 %0, %1;" : "=f"(r) : "f"(x));
    return r;
}

__device__ __forceinline__ uint32_t pack_f16x2(float lo, float hi) {
    uint32_t r;
    asm("cvt.rn.f16x2.f32 %0, %1, %2;" : "=r"(r) : "f"(hi), "f"(lo));
    return r;
}

__device__ __forceinline__ void mma_f16(float c[4], const uint32_t a[4],
                                        uint32_t b0, uint32_t b1) {
    asm volatile(
        "mma.sync.aligned.m16n8k16.row.col.f32.f16.f16.f32 "
        "{%0,%1,%2,%3}, {%4,%5,%6,%7}, {%8,%9}, {%0,%1,%2,%3};"
        : "+f"(c[0]), "+f"(c[1]), "+f"(c[2]), "+f"(c[3])
        : "r"(a[0]), "r"(a[1]), "r"(a[2]), "r"(a[3]), "r"(b0), "r"(b1));
}

__device__ __forceinline__ void cp16(void* s, const void* gp) {
    uint32_t sa = (uint32_t)__cvta_generic_to_shared(s);
    asm volatile("cp.async.cg.shared.global [%0], [%1], 16;" :: "r"(sa), "l"(gp));
}
__device__ __forceinline__ void cp_commit() {
    asm volatile("cp.async.commit_group;");
}
__device__ __forceinline__ void cp_wait_all() {
    asm volatile("cp.async.wait_group 0;");
}

// ---------------------------------------------------------------------------
// Kernel 0a: X -> fp16 fragment-quad layout
// ---------------------------------------------------------------------------
__global__ void perm_x(const float* __restrict__ X)
{
    int i = blockIdx.x * blockDim.x + threadIdx.x;    // 524288 total
    int lane = i & 31;
    int t = lane & 3, g = lane >> 2;
    int kb = (i >> 5) & 63;
    int mb = i >> 11;
    const float* s = X + (size_t)(mb * 16) * DMODEL + kb * 16;
    uint32_t a0 = pack_f16x2(s[(size_t)g * DMODEL + 2*t],       s[(size_t)g * DMODEL + 2*t + 1]);
    uint32_t a1 = pack_f16x2(s[(size_t)(g+8) * DMODEL + 2*t],   s[(size_t)(g+8) * DMODEL + 2*t + 1]);
    uint32_t a2 = pack_f16x2(s[(size_t)g * DMODEL + 2*t + 8],   s[(size_t)g * DMODEL + 2*t + 9]);
    uint32_t a3 = pack_f16x2(s[(size_t)(g+8) * DMODEL + 2*t+8], s[(size_t)(g+8) * DMODEL + 2*t + 9]);
    reinterpret_cast<uint4*>(g_X)[i] = make_uint4(a0, a1, a2, a3);
}

// Kernel 0b: W -> fp16 k-pair layout; blockIdx.y selects matrix
__global__ void perm_w(const float* __restrict__ w0,
                       const float* __restrict__ w1,
                       const float* __restrict__ w2)
{
    const float* src = (blockIdx.y == 0) ? w0 : (blockIdx.y == 1) ? w1 : w2;
    uint2* dst = reinterpret_cast<uint2*>(g_W) + (size_t)blockIdx.y * 262144;
    int i = blockIdx.x * blockDim.x + threadIdx.x;    // 262144 total
    int t = i & 3;
    int n = (i >> 2) & 1023;
    int kb = i >> 12;
    uint32_t r0 = pack_f16x2(src[(size_t)(kb*16 + 2*t)     * DMODEL + n],
                             src[(size_t)(kb*16 + 2*t + 1) * DMODEL + n]);
    uint32_t r1 = pack_f16x2(src[(size_t)(kb*16 + 2*t + 8) * DMODEL + n],
                             src[(size_t)(kb*16 + 2*t + 9) * DMODEL + n]);
    dst[i] = make_uint2(r0, r1);
}

// ---------------------------------------------------------------------------
// Kernel 1: QKV projection, fp16 m16n8k16, fp32 accum.
// BM=256, BN=128, BK=32 (2 k16 steps). 8 warps as 4x2, warp tile 64x64.
// A: LDS.128 per (fm,ks). B: LDS.64 per (fn,ks). cp.async double buffer.
// Epilogue: Q/K fp16 pair rows (+QSCALE for Q), V fp16 pair-interleaved.
// ---------------------------------------------------------------------------
#define BM 256
#define BN 128
#define GEMM_SMEM_BYTES (2 * (16384 + 8192))   // 49152
#define NKTILES 32
#define QSCALE  0.18033688011112042f   // 0.125 * log2(e)

__global__ __launch_bounds__(256, 1)
void qkv_gemm_kernel(const float* __restrict__ bq,
                     const float* __restrict__ bk,
                     const float* __restrict__ bv)
{
    extern __shared__ uint32_t sg[];
    uint4* As = reinterpret_cast<uint4*>(sg);            // 2 x 1024 uint4
    uint2* Bs = reinterpret_cast<uint2*>(sg + 2 * 4096); // 2 x 1024 uint2

    const uint2* Wp = reinterpret_cast<const uint2*>(g_W) + (size_t)blockIdx.z * 262144;
    const float* bias = (blockIdx.z == 0) ? bq : (blockIdx.z == 1) ? bk : bv;

    const int m0 = blockIdx.y * BM;
    const int n0 = blockIdx.x * BN;
    const int tid  = threadIdx.x;
    const int lane = tid & 31;
    const int warp = tid >> 5;
    const int g = lane >> 2;
    const int t = lane & 3;
    const int wm = warp >> 1;     // 0..3 -> rows 64*wm
    const int wn = warp & 1;      // 0..1 -> cols 64*wn
    const int m0b = m0 >> 4;

    auto load_ktile = [&](int kt, int buf) {
        uint4* Ab = As + buf * 1024;
        uint2* Bb = Bs + buf * 1024;
        const int kb0 = kt * 2;
        #pragma unroll
        for (int it = 0; it < 4; it++) {
            int idx = tid + it * 256;
            int lc = idx & 31, kb = (idx >> 5) & 1, mb = idx >> 6;
            const uint4* src = reinterpret_cast<const uint4*>(g_X) +
                ((size_t)(m0b + mb) * 64 + kb0 + kb) * 32 + lc;
            cp16(&Ab[(mb * 2 + kb) * 32 + lc], src);
        }
        #pragma unroll
        for (int it = 0; it < 2; it++) {
            int idx = tid + it * 256;
            int kb = idx >> 8, rem = idx & 255;
            int nl = rem >> 1, t2 = (rem & 1) * 2;
            const uint2* src = Wp + ((size_t)(kb0 + kb) * 1024 + n0 + nl) * 4 + t2;
            cp16(&Bb[(kb * 128 + nl) * 4 + t2], src);
        }
        cp_commit();
    };

    load_ktile(0, 0);

    float acc[4][8][4];
    #pragma unroll
    for (int fm = 0; fm < 4; fm++)
        #pragma unroll
        for (int fn = 0; fn < 8; fn++)
            #pragma unroll
            for (int e = 0; e < 4; e++) acc[fm][fn][e] = 0.0f;

    for (int kt = 0; kt < NKTILES; kt++) {
        const int buf = kt & 1;
        cp_wait_all();
        __syncthreads();

        if (kt + 1 < NKTILES) load_ktile(kt + 1, buf ^ 1);

        const uint4* Ab = As + buf * 1024;
        const uint2* Bb = Bs + buf * 1024;

        #pragma unroll
        for (int ks = 0; ks < 2; ks++) {
            uint32_t a[4][4];
            #pragma unroll
            for (int fm = 0; fm < 4; fm++) {
                uint4 av = Ab[((wm * 4 + fm) * 2 + ks) * 32 + lane];
                a[fm][0] = av.x; a[fm][1] = av.y; a[fm][2] = av.z; a[fm][3] = av.w;
            }
            #pragma unroll
            for (int fn = 0; fn < 8; fn++) {
                uint2 bp = Bb[(ks * 128 + wn * 64 + fn * 8 + g) * 4 + t];
                #pragma unroll
                for (int fm = 0; fm < 4; fm++) mma_f16(acc[fm][fn], a[fm], bp.x, bp.y);
            }
        }
        __syncthreads();
    }

    const int b  = m0 / SEQ;
    const int s0 = m0 % SEQ;
    const int h0 = n0 >> 6;

    if (blockIdx.z == 2) {
        // V fp16 pair-interleaved
        __half* gV = reinterpret_cast<__half*>(g_V);
        #pragma unroll
        for (int fm = 0; fm < 4; fm++) {
            int r0 = wm * 64 + fm * 16 + g;
            #pragma unroll
            for (int fn = 0; fn < 8; fn++) {
                int c = wn * 64 + fn * 8 + 2 * t;
                int h = h0 + (c >> 6);
                int cc = c & 63;
                float bv0 = bias[n0 + c];
                float bv1 = bias[n0 + c + 1];
                __half* base = gV + (size_t)(b * NHEADS + h) * SEQ * DK;
                int sA = s0 + r0;
                int sB = sA + 8;
                int k2A = (sA & 15) >> 1, pA = 2 * (k2A & 3) + (k2A >> 2);
                int k2B = (sB & 15) >> 1, pB = 2 * (k2B & 3) + (k2B >> 2);
                size_t gA = ((size_t)(sA >> 4) * 64) * 16 + pA * 2 + (sA & 1);
                size_t gB = ((size_t)(sB >> 4) * 64) * 16 + pB * 2 + (sB & 1);
                base[gA + (size_t)cc * 16]       = __float2half(acc[fm][fn][0] + bv0);
                base[gA + (size_t)(cc + 1) * 16] = __float2half(acc[fm][fn][1] + bv1);
                base[gB + (size_t)cc * 16]       = __float2half(acc[fm][fn][2] + bv0);
                base[gB + (size_t)(cc + 1) * 16] = __float2half(acc[fm][fn][3] + bv1);
            }
        }
    } else {
        // Q (scaled) or K: fp16 pair rows, one uint32 per (row, pair)
        uint32_t* Out = reinterpret_cast<uint32_t*>(blockIdx.z == 0 ? g_Q : g_K);
        const float scale = (blockIdx.z == 0) ? QSCALE : 1.0f;
        #pragma unroll
        for (int fm = 0; fm < 4; fm++) {
            int r0 = wm * 64 + fm * 16 + g;
            #pragma unroll
            for (int fn = 0; fn < 8; fn++) {
                int c = wn * 64 + fn * 8 + 2 * t;
                int h = h0 + (c >> 6);
                int cc = c & 63;
                int j = (cc >> 1) & 7;
                int idx32 = (cc >> 4) * 8 + 2 * (j & 3) + (j >> 2);
                float bv0 = bias[n0 + c];
                float bv1 = bias[n0 + c + 1];
                uint32_t* ob = Out + ((size_t)(b * NHEADS + h) * SEQ + s0) * 32;
                ob[(size_t)(r0)     * 32 + idx32] =
                    pack_f16x2((acc[fm][fn][0] + bv0) * scale, (acc[fm][fn][1] + bv1) * scale);
                ob[(size_t)(r0 + 8) * 32 + idx32] =
                    pack_f16x2((acc[fm][fn][2] + bv0) * scale, (acc[fm][fn][3] + bv1) * scale);
            }
        }
    }
}

// ---------------------------------------------------------------------------
// Kernel 2: flash attention, fully fp16 MMA (m16n8k16, fp32 accum).
// QT=256, 8 warps x 32 rows. S: Q(frag regs) x K(pair rows, LDS.64).
// P packs straight from S accumulators (no shuffles). PV as R14.
// ---------------------------------------------------------------------------
#define QT   256
#define KSTR32 36                     // uint32 stride per K/Q row (144B)
#define NKT  (SEQ / 64)
#define ATTN_SMEM_BYTES (256 * KSTR32 * 4)   // 36864 (staging superset)

__global__ __launch_bounds__(256, 1)
void attn_kernel(float* __restrict__ out)
{
    extern __shared__ uint32_t smu[];
    uint32_t* Ks = smu;                     // 2 bufs x 64 x KSTR32
    uint32_t* Vs = smu + 2 * 64 * KSTR32;   // 2 bufs x 2048

    const int bh = blockIdx.y;
    const int b  = bh >> 4;
    const int h  = bh & 15;
    const int q0 = blockIdx.x * QT;

    const uint32_t* Qp = reinterpret_cast<const uint32_t*>(g_Q) + ((size_t)bh * SEQ + q0) * 32;
    const uint32_t* Kp = reinterpret_cast<const uint32_t*>(g_K) + (size_t)bh * SEQ * 32;
    const char*     Vp = reinterpret_cast<const char*>(g_V) + (size_t)bh * SEQ * DK * 2;

    const int tid  = threadIdx.x;
    const int lane = tid & 31;
    const int warp = tid >> 5;
    const int g = lane >> 2;
    const int t = lane & 3;
    const int row0 = warp * 32;

    // Stage all 256 Q rows (32 uint32 each) into smem, stride KSTR32
    #pragma unroll
    for (int it = 0; it < 8; it++) {
        int idx = tid + it * 256;           // 2048 x 16B
        int r = idx >> 3, ch = idx & 7;
        *reinterpret_cast<uint4*>(&smu[r * KSTR32 + ch * 4]) =
            *reinterpret_cast<const uint4*>(Qp + (size_t)r * 32 + ch * 4);
    }
    __syncthreads();

    uint32_t qfA[4][4], qfB[4][4];
    #pragma unroll
    for (int ks = 0; ks < 4; ks++) {
        uint2 u0 = *reinterpret_cast<const uint2*>(&smu[(row0 + g)      * KSTR32 + ks * 8 + 2 * t]);
        uint2 u1 = *reinterpret_cast<const uint2*>(&smu[(row0 + g + 8)  * KSTR32 + ks * 8 + 2 * t]);
        qfA[ks][0] = u0.x; qfA[ks][1] = u1.x; qfA[ks][2] = u0.y; qfA[ks][3] = u1.y;
        uint2 v0 = *reinterpret_cast<const uint2*>(&smu[(row0 + g + 16) * KSTR32 + ks * 8 + 2 * t]);
        uint2 v1 = *reinterpret_cast<const uint2*>(&smu[(row0 + g + 24) * KSTR32 + ks * 8 + 2 * t]);
        qfB[ks][0] = v0.x; qfB[ks][1] = v1.x; qfB[ks][2] = v0.y; qfB[ks][3] = v1.y;
    }
    __syncthreads();

    // Tile loader: K 8KB (512 x 16B), V 8KB (512 x 16B)
    auto load_tile = [&](int kt, int buf) {
        uint32_t* Kb = Ks + buf * 64 * KSTR32;
        uint32_t* Vb = Vs + buf * 2048;
        const uint32_t* kp = Kp + (size_t)kt * 64 * 32;
        const char* vp = Vp + (size_t)kt * 8192;
        #pragma unroll
        for (int it = 0; it < 2; it++) {
            int idx = tid + it * 256;
            int r = idx >> 3, ch = idx & 7;
            cp16(&Kb[r * KSTR32 + ch * 4], kp + (size_t)r * 32 + ch * 4);
        }
        #pragma unroll
        for (int it = 0; it < 2; it++) {
            int idx = tid + it * 256;
            cp16(&Vb[idx * 4], vp + (size_t)idx * 16);
        }
        cp_commit();
    };

    load_tile(0, 0);

    float oaccA[8][4], oaccB[8][4];
    #pragma unroll
    for (int jn = 0; jn < 8; jn++)
        #pragma unroll
        for (int e = 0; e < 4; e++) { oaccA[jn][e] = 0.0f; oaccB[jn][e] = 0.0f; }
    float rsA0 = 0.0f, rsA1 = 0.0f, rsB0 = 0.0f, rsB1 = 0.0f;

    for (int kt = 0; kt < NKT; kt++) {
        const int buf = kt & 1;
        cp_wait_all();
        __syncthreads();

        if (kt + 1 < NKT) load_tile(kt + 1, buf ^ 1);

        const uint32_t* Kb = Ks + buf * 64 * KSTR32;
        const uint32_t* Vb = Vs + buf * 2048;

        #pragma unroll
        for (int j2 = 0; j2 < 4; j2++) {
            float sEA[4] = {0.f,0.f,0.f,0.f}, sEB[4] = {0.f,0.f,0.f,0.f};
            float sOA[4] = {0.f,0.f,0.f,0.f}, sOB[4] = {0.f,0.f,0.f,0.f};
            #pragma unroll
            for (int ks = 0; ks < 4; ks++) {
                int keyE = j2 * 16 + g;
                uint2 kE = *reinterpret_cast<const uint2*>(&Kb[keyE * KSTR32 + ks * 8 + 2 * t]);
                uint2 kO = *reinterpret_cast<const uint2*>(&Kb[(keyE + 8) * KSTR32 + ks * 8 + 2 * t]);
                mma_f16(sEA, qfA[ks], kE.x, kE.y);
                mma_f16(sEB, qfB[ks], kE.x, kE.y);
                mma_f16(sOA, qfA[ks], kO.x, kO.y);
                mma_f16(sOB, qfB[ks], kO.x, kO.y);
            }

            // exp2 (log2 domain), rowsums, pack to fp16 A-fragments
            uint32_t aA[4], aB[4];
            {
                float e0 = ex2f(sEA[0]), e1 = ex2f(sEA[1]);
                float e2 = ex2f(sEA[2]), e3 = ex2f(sEA[3]);
                float o0 = ex2f(sOA[0]), o1 = ex2f(sOA[1]);
                float o2 = ex2f(sOA[2]), o3 = ex2f(sOA[3]);
                rsA0 += e0 + e1 + o0 + o1;
                rsA1 += e2 + e3 + o2 + o3;
                aA[0] = pack_f16x2(e0, e1);
                aA[1] = pack_f16x2(e2, e3);
                aA[2] = pack_f16x2(o0, o1);
                aA[3] = pack_f16x2(o2, o3);
            }
            {
                float e0 = ex2f(sEB[0]), e1 = ex2f(sEB[1]);
                float e2 = ex2f(sEB[2]), e3 = ex2f(sEB[3]);
                float o0 = ex2f(sOB[0]), o1 = ex2f(sOB[1]);
                float o2 = ex2f(sOB[2]), o3 = ex2f(sOB[3]);
                rsB0 += e0 + e1 + o0 + o1;
                rsB1 += e2 + e3 + o2 + o3;
                aB[0] = pack_f16x2(e0, e1);
                aB[1] = pack_f16x2(e2, e3);
                aB[2] = pack_f16x2(o0, o1);
                aB[3] = pack_f16x2(o2, o3);
            }

            // PV: V pair-interleaved (LDS.64)
            #pragma unroll
            for (int jn = 0; jn < 8; jn++) {
                int dcol = jn * 8 + g;
                uint2 bv = *reinterpret_cast<const uint2*>(&Vb[(j2 * 64 + dcol) * 8 + 2 * t]);
                mma_f16(oaccA[jn], aA, bv.x, bv.y);
                mma_f16(oaccB[jn], aB, bv.x, bv.y);
            }
        }
    }

    rsA0 += __shfl_xor_sync(0xffffffffu, rsA0, 1);
    rsA0 += __shfl_xor_sync(0xffffffffu, rsA0, 2);
    rsA1 += __shfl_xor_sync(0xffffffffu, rsA1, 1);
    rsA1 += __shfl_xor_sync(0xffffffffu, rsA1, 2);
    rsB0 += __shfl_xor_sync(0xffffffffu, rsB0, 1);
    rsB0 += __shfl_xor_sync(0xffffffffu, rsB0, 2);
    rsB1 += __shfl_xor_sync(0xffffffffu, rsB1, 1);
    rsB1 += __shfl_xor_sync(0xffffffffu, rsB1, 2);
    float invA0 = 1.0f / (rsA0 + 1e-8f);
    float invA1 = 1.0f / (rsA1 + 1e-8f);
    float invB0 = 1.0f / (rsB0 + 1e-8f);
    float invB1 = 1.0f / (rsB1 + 1e-8f);

    #pragma unroll
    for (int jn = 0; jn < 8; jn++) {
        int dcol = jn * 8 + 2 * t;
        float* base = out + ((size_t)(b * SEQ + q0 + row0 + g)) * DMODEL + h * DK + dcol;
        *reinterpret_cast<float2*>(base) =
            make_float2(oaccA[jn][0] * invA0, oaccA[jn][1] * invA0);
        *reinterpret_cast<float2*>(base + (size_t)8 * DMODEL) =
            make_float2(oaccA[jn][2] * invA1, oaccA[jn][3] * invA1);
        *reinterpret_cast<float2*>(base + (size_t)16 * DMODEL) =
            make_float2(oaccB[jn][0] * invB0, oaccB[jn][1] * invB0);
        *reinterpret_cast<float2*>(base + (size_t)24 * DMODEL) =
            make_float2(oaccB[jn][2] * invB1, oaccB[jn][3] * invB1);
    }
}

// ---------------------------------------------------------------------------
extern "C" void kernel_launch(void* const* d_in, const int* in_sizes, int n_in,
                              void* d_out, int out_size)
{
    const float* x  = (const float*)d_in[0];
    const float* Wq = (const float*)d_in[1];
    const float* bq = (const float*)d_in[2];
    const float* Wk = (const float*)d_in[3];
    const float* bk = (const float*)d_in[4];
    const float* Wv = (const float*)d_in[5];
    const float* bv = (const float*)d_in[6];
    float* out = (float*)d_out;

    cudaFuncSetAttribute(attn_kernel, cudaFuncAttributeMaxDynamicSharedMemorySize,
                         (int)ATTN_SMEM_BYTES);
    cudaFuncSetAttribute(qkv_gemm_kernel, cudaFuncAttributeMaxDynamicSharedMemorySize,
                         (int)GEMM_SMEM_BYTES);

    perm_x<<<524288 / 256, 256>>>(x);
    dim3 wgrid(262144 / 256, 3);
    perm_w<<<wgrid, 256>>>(Wq, Wk, Wv);

    dim3 gemm_grid(DMODEL / BN, MTOT / BM, 3);   // 8 x 16 x 3
    qkv_gemm_kernel<<<gemm_grid, 256, GEMM_SMEM_BYTES>>>(bq, bk, bv);

    dim3 attn_grid(SEQ / QT, BH);                // 8 x 32
    attn_kernel<<<attn_grid, 256, ATTN_SMEM_BYTES>>>(out);
}